// round 3
// baseline (speedup 1.0000x reference)
#include <cuda_runtime.h>
#include <cuda_bf16.h>
#include <cstdint>
#include <cstddef>

// ---------------------------------------------------------------------------
// Problem constants
// ---------------------------------------------------------------------------
#define B_SZ   4
#define NH_    4
#define HD_    32
#define C_DIM  128
#define WS_    8
#define L_WIN  64
#define NWIN   1024        // windows per batch image (32 x 32)
#define N_IMG  65536       // 256*256
#define TD_    100
#define T_TOT  65736       // 65536 + 100 + 100
#define M_TOT  (B_SZ * T_TOT)   // 262944 rows total
#define SCALE_ 0.17677669529663687f   // 32^-0.5

// Scratch (device globals -- no allocation allowed in kernel_launch)
__device__ float g_qkv[(size_t)M_TOT * 384];   // [row][3*C] with channel = s*128 + h*32 + d
__device__ float g_ctx[(size_t)M_TOT * 128];   // attention outputs, proj input

// ---------------------------------------------------------------------------
// Row pointer for the concatenated token matrix [x | det | inter] per batch
// ---------------------------------------------------------------------------
__device__ __forceinline__ const float* token_row(int r,
                                                  const float* __restrict__ x,
                                                  const float* __restrict__ det,
                                                  const float* __restrict__ inter)
{
    int b = r / T_TOT;
    int t = r - b * T_TOT;
    if (t < N_IMG)  return x     + ((size_t)b * N_IMG + t) * C_DIM;
    t -= N_IMG;
    if (t < TD_)    return det   + ((size_t)b * TD_   + t) * C_DIM;
    return inter + ((size_t)b * TD_ + (t - TD_)) * C_DIM;
}

// ---------------------------------------------------------------------------
// K1: QKV GEMM  out[r][o] = sum_k tokens[r][k] * Wq[o][k] + bq[o]
//     M = 262944, N = 384, K = 128. 128x128 block tile, 8x8 microtile.
// ---------------------------------------------------------------------------
__global__ __launch_bounds__(256, 2)
void qkv_gemm_kernel(const float* __restrict__ x, const float* __restrict__ det,
                     const float* __restrict__ inter, const float* __restrict__ Wq,
                     const float* __restrict__ bq)
{
    __shared__ __align__(16) float As[32][132];   // [k][m]
    __shared__ __align__(16) float Bs[32][132];   // [k][n]
    const int m0 = blockIdx.y * 128;
    const int n0 = blockIdx.x * 128;
    const int tid = threadIdx.x;
    const int tx = tid & 15, ty = tid >> 4;
    float acc[8][8] = {};

    for (int kk = 0; kk < 128; kk += 32) {
        #pragma unroll
        for (int it = 0; it < 4; it++) {
            int idx = tid + it * 256;          // 0..1023
            int row = idx >> 3;                // 0..127
            int c4  = (idx & 7) * 4;           // 0,4,...,28
            int r = m0 + row;
            float4 av = make_float4(0.f, 0.f, 0.f, 0.f);
            if (r < M_TOT) {
                const float* ap = token_row(r, x, det, inter);
                av = *(const float4*)(ap + kk + c4);
            }
            As[c4 + 0][row] = av.x; As[c4 + 1][row] = av.y;
            As[c4 + 2][row] = av.z; As[c4 + 3][row] = av.w;
            float4 bv = *(const float4*)(Wq + (size_t)(n0 + row) * 128 + kk + c4);
            Bs[c4 + 0][row] = bv.x; Bs[c4 + 1][row] = bv.y;
            Bs[c4 + 2][row] = bv.z; Bs[c4 + 3][row] = bv.w;
        }
        __syncthreads();
        #pragma unroll
        for (int k = 0; k < 32; k++) {
            float4 a0 = *(const float4*)&As[k][ty * 8];
            float4 a1 = *(const float4*)&As[k][ty * 8 + 4];
            float4 b0 = *(const float4*)&Bs[k][tx * 8];
            float4 b1 = *(const float4*)&Bs[k][tx * 8 + 4];
            float a[8] = {a0.x, a0.y, a0.z, a0.w, a1.x, a1.y, a1.z, a1.w};
            float b[8] = {b0.x, b0.y, b0.z, b0.w, b1.x, b1.y, b1.z, b1.w};
            #pragma unroll
            for (int i = 0; i < 8; i++)
                #pragma unroll
                for (int j = 0; j < 8; j++)
                    acc[i][j] += a[i] * b[j];
        }
        __syncthreads();
    }

    float4 bias0 = *(const float4*)(bq + n0 + tx * 8);
    float4 bias1 = *(const float4*)(bq + n0 + tx * 8 + 4);
    #pragma unroll
    for (int i = 0; i < 8; i++) {
        int r = m0 + ty * 8 + i;
        if (r < M_TOT) {
            float4 o0 = make_float4(acc[i][0] + bias0.x, acc[i][1] + bias0.y,
                                    acc[i][2] + bias0.z, acc[i][3] + bias0.w);
            float4 o1 = make_float4(acc[i][4] + bias1.x, acc[i][5] + bias1.y,
                                    acc[i][6] + bias1.z, acc[i][7] + bias1.w);
            float* op = g_qkv + (size_t)r * 384 + n0 + tx * 8;
            *(float4*)op       = o0;
            *(float4*)(op + 4) = o1;
        }
    }
}

// ---------------------------------------------------------------------------
// K2: windowed attention. One block per (head, window, batch). 256 threads.
//     S = (q k^T) * scale + bias[h] + mask[w]; P = softmax(S); O = P v.
// ---------------------------------------------------------------------------
__global__ void win_attn_kernel(const float* __restrict__ mask,
                                const float* __restrict__ rel_table,
                                const int*   __restrict__ rel_index)
{
    const int h  = blockIdx.x;   // 0..3
    const int w  = blockIdx.y;   // 0..1023 (hy*32 + wx)
    const int b  = blockIdx.z;   // 0..3
    const int hy = w >> 5, wx = w & 31;
    const int tid = threadIdx.x;

    __shared__ __align__(16) float qs[64][36];
    __shared__ __align__(16) float ks[64][36];
    __shared__ __align__(16) float vs[64][36];
    __shared__ __align__(16) float Ss[64][68];

    // --- load q,k,v tiles: 3 * 64 tokens * 32 floats ---
    #pragma unroll
    for (int it = 0; it < 6; it++) {
        int idx = tid + it * 256;        // 0..1535
        int mtx = idx / 512;             // 0=q 1=k 2=v
        int rem = idx - mtx * 512;
        int tok = rem >> 3;              // 0..63 (= i*8 + j)
        int c4  = (rem & 7) * 4;
        int wi = tok >> 3, wj = tok & 7;
        int t = (hy * 8 + wi) * 256 + (wx * 8 + wj);
        size_t base = ((size_t)(b * T_TOT + t)) * 384 + (size_t)mtx * 128 + h * 32;
        float4 v4 = *(const float4*)(g_qkv + base + c4);
        float* dst = (mtx == 0) ? &qs[0][0] : (mtx == 1) ? &ks[0][0] : &vs[0][0];
        *(float4*)(dst + tok * 36 + c4) = v4;
    }
    __syncthreads();

    // --- S = q k^T : 4x4 microtile per thread over the 64x64 score matrix ---
    {
        const int tr = tid >> 4, tc = tid & 15;
        const int r0 = tr * 4, c0 = tc * 4;
        float acc[4][4] = {};
        #pragma unroll
        for (int d4 = 0; d4 < 8; d4++) {
            float4 qv[4], kv[4];
            #pragma unroll
            for (int i = 0; i < 4; i++) qv[i] = *(const float4*)&qs[r0 + i][d4 * 4];
            #pragma unroll
            for (int j = 0; j < 4; j++) kv[j] = *(const float4*)&ks[c0 + j][d4 * 4];
            #pragma unroll
            for (int i = 0; i < 4; i++)
                #pragma unroll
                for (int j = 0; j < 4; j++)
                    acc[i][j] += qv[i].x * kv[j].x + qv[i].y * kv[j].y
                               + qv[i].z * kv[j].z + qv[i].w * kv[j].w;
        }
        #pragma unroll
        for (int i = 0; i < 4; i++)
            *(float4*)&Ss[r0 + i][c0] =
                make_float4(acc[i][0], acc[i][1], acc[i][2], acc[i][3]);
    }
    __syncthreads();

    // --- softmax rows: 4 threads per row, 16 cols each ---
    {
        const int r   = tid >> 2;
        const int seg = tid & 3;
        const int cb  = seg * 16;
        const float* mrow = mask + ((size_t)w * 64 + r) * 64 + cb;
        const int*   irow = rel_index + r * 64 + cb;
        float sv[16];
        float mx = -1e30f;
        #pragma unroll
        for (int jj = 0; jj < 16; jj++) {
            float s = Ss[r][cb + jj] * SCALE_ + rel_table[irow[jj] * 4 + h] + mrow[jj];
            sv[jj] = s;
            mx = fmaxf(mx, s);
        }
        mx = fmaxf(mx, __shfl_xor_sync(0xffffffffu, mx, 1));
        mx = fmaxf(mx, __shfl_xor_sync(0xffffffffu, mx, 2));
        float sum = 0.f;
        #pragma unroll
        for (int jj = 0; jj < 16; jj++) {
            sv[jj] = __expf(sv[jj] - mx);
            sum += sv[jj];
        }
        sum += __shfl_xor_sync(0xffffffffu, sum, 1);
        sum += __shfl_xor_sync(0xffffffffu, sum, 2);
        float inv = 1.0f / sum;
        #pragma unroll
        for (int jj = 0; jj < 16; jj++)
            Ss[r][cb + jj] = sv[jj] * inv;
    }
    __syncthreads();

    // --- O = P v : 2 rows x 4 d per thread ---
    {
        const int trr = tid >> 3;        // 0..31 -> rows 2*trr, 2*trr+1
        const int td  = tid & 7;         // cols td*4 .. td*4+3
        float o0[4] = {}, o1[4] = {};
        #pragma unroll 16
        for (int j = 0; j < 64; j++) {
            float p0 = Ss[2 * trr][j];
            float p1 = Ss[2 * trr + 1][j];
            float4 vv = *(const float4*)&vs[j][td * 4];
            o0[0] += p0 * vv.x; o0[1] += p0 * vv.y; o0[2] += p0 * vv.z; o0[3] += p0 * vv.w;
            o1[0] += p1 * vv.x; o1[1] += p1 * vv.y; o1[2] += p1 * vv.z; o1[3] += p1 * vv.w;
        }
        #pragma unroll
        for (int rr = 0; rr < 2; rr++) {
            int l = 2 * trr + rr;
            int wi = l >> 3, wj = l & 7;
            int t = (hy * 8 + wi) * 256 + (wx * 8 + wj);
            float* op = g_ctx + ((size_t)(b * T_TOT + t)) * 128 + h * 32 + td * 4;
            const float* src = rr ? o1 : o0;
            *(float4*)op = make_float4(src[0], src[1], src[2], src[3]);
        }
    }
}

// ---------------------------------------------------------------------------
// K3: det/inter token MHA. One block per (head, batch, type). 128 threads,
//     one thread owns one of the 100 query rows.
// ---------------------------------------------------------------------------
__global__ void tok_attn_kernel()
{
    const int h  = blockIdx.x;
    const int b  = blockIdx.y;
    const int ty = blockIdx.z;           // 0 = det, 1 = inter
    const int tid = threadIdx.x;
    const int tbase = N_IMG + ty * TD_;

    __shared__ __align__(16) float ks[100][32];
    __shared__ __align__(16) float vs[100][32];

    for (int idx = tid; idx < 100 * 8; idx += 128) {
        int tok = idx >> 3;
        int c4  = (idx & 7) * 4;
        size_t base = ((size_t)(b * T_TOT + tbase + tok)) * 384 + h * 32;
        *(float4*)&ks[tok][c4] = *(const float4*)(g_qkv + base + 128 + c4);
        *(float4*)&vs[tok][c4] = *(const float4*)(g_qkv + base + 256 + c4);
    }
    __syncthreads();

    if (tid < 100) {
        const int r = tid;
        float q[32];
        const float* qp = g_qkv + ((size_t)(b * T_TOT + tbase + r)) * 384 + h * 32;
        #pragma unroll
        for (int d = 0; d < 32; d++) q[d] = qp[d] * SCALE_;

        float srow[100];
        float mx = -1e30f;
        for (int j = 0; j < 100; j++) {
            float s = 0.f;
            #pragma unroll
            for (int d = 0; d < 32; d++) s += q[d] * ks[j][d];
            srow[j] = s;
            mx = fmaxf(mx, s);
        }
        float sum = 0.f;
        for (int j = 0; j < 100; j++) {
            srow[j] = __expf(srow[j] - mx);
            sum += srow[j];
        }
        float inv = 1.0f / sum;
        float o[32] = {};
        for (int j = 0; j < 100; j++) {
            float p = srow[j] * inv;
            #pragma unroll
            for (int d = 0; d < 32; d++) o[d] += p * vs[j][d];
        }
        float* op = g_ctx + ((size_t)(b * T_TOT + tbase + r)) * 128 + h * 32;
        #pragma unroll
        for (int d = 0; d < 32; d++) op[d] = o[d];
    }
}

// ---------------------------------------------------------------------------
// K4: projection GEMM  out[r][o] = sum_k ctx[r][k] * Wp[o][k] + bp[o]
//     M = 262944, N = 128, K = 128. Same scheme as K1.
// ---------------------------------------------------------------------------
__global__ __launch_bounds__(256, 2)
void proj_gemm_kernel(const float* __restrict__ Wp, const float* __restrict__ bp,
                      float* __restrict__ out)
{
    __shared__ __align__(16) float As[32][132];
    __shared__ __align__(16) float Bs[32][132];
    const int m0 = blockIdx.y * 128;
    const int n0 = blockIdx.x * 128;   // always 0 (N=128)
    const int tid = threadIdx.x;
    const int tx = tid & 15, ty = tid >> 4;
    float acc[8][8] = {};

    for (int kk = 0; kk < 128; kk += 32) {
        #pragma unroll
        for (int it = 0; it < 4; it++) {
            int idx = tid + it * 256;
            int row = idx >> 3;
            int c4  = (idx & 7) * 4;
            int r = m0 + row;
            float4 av = make_float4(0.f, 0.f, 0.f, 0.f);
            if (r < M_TOT)
                av = *(const float4*)(g_ctx + (size_t)r * 128 + kk + c4);
            As[c4 + 0][row] = av.x; As[c4 + 1][row] = av.y;
            As[c4 + 2][row] = av.z; As[c4 + 3][row] = av.w;
            float4 bv = *(const float4*)(Wp + (size_t)(n0 + row) * 128 + kk + c4);
            Bs[c4 + 0][row] = bv.x; Bs[c4 + 1][row] = bv.y;
            Bs[c4 + 2][row] = bv.z; Bs[c4 + 3][row] = bv.w;
        }
        __syncthreads();
        #pragma unroll
        for (int k = 0; k < 32; k++) {
            float4 a0 = *(const float4*)&As[k][ty * 8];
            float4 a1 = *(const float4*)&As[k][ty * 8 + 4];
            float4 b0 = *(const float4*)&Bs[k][tx * 8];
            float4 b1 = *(const float4*)&Bs[k][tx * 8 + 4];
            float a[8] = {a0.x, a0.y, a0.z, a0.w, a1.x, a1.y, a1.z, a1.w};
            float b[8] = {b0.x, b0.y, b0.z, b0.w, b1.x, b1.y, b1.z, b1.w};
            #pragma unroll
            for (int i = 0; i < 8; i++)
                #pragma unroll
                for (int j = 0; j < 8; j++)
                    acc[i][j] += a[i] * b[j];
        }
        __syncthreads();
    }

    float4 bias0 = *(const float4*)(bp + n0 + tx * 8);
    float4 bias1 = *(const float4*)(bp + n0 + tx * 8 + 4);
    #pragma unroll
    for (int i = 0; i < 8; i++) {
        int r = m0 + ty * 8 + i;
        if (r < M_TOT) {
            float4 o0 = make_float4(acc[i][0] + bias0.x, acc[i][1] + bias0.y,
                                    acc[i][2] + bias0.z, acc[i][3] + bias0.w);
            float4 o1 = make_float4(acc[i][4] + bias1.x, acc[i][5] + bias1.y,
                                    acc[i][6] + bias1.z, acc[i][7] + bias1.w);
            float* op = out + (size_t)r * 128 + n0 + tx * 8;
            *(float4*)op       = o0;
            *(float4*)(op + 4) = o1;
        }
    }
}

// ---------------------------------------------------------------------------
// kernel_launch
// Inputs (metadata order): x, det, inter, mask, W_qkv, b_qkv, W_proj, b_proj,
//                          rel_table, rel_index
// ---------------------------------------------------------------------------
extern "C" void kernel_launch(void* const* d_in, const int* in_sizes, int n_in,
                              void* d_out, int out_size)
{
    (void)in_sizes; (void)n_in; (void)out_size;
    const float* x        = (const float*)d_in[0];
    const float* det      = (const float*)d_in[1];
    const float* inter    = (const float*)d_in[2];
    const float* mask     = (const float*)d_in[3];
    const float* W_qkv    = (const float*)d_in[4];
    const float* b_qkv    = (const float*)d_in[5];
    const float* W_proj   = (const float*)d_in[6];
    const float* b_proj   = (const float*)d_in[7];
    const float* rel_tab  = (const float*)d_in[8];
    const int*   rel_idx  = (const int*)d_in[9];
    float* out = (float*)d_out;

    const int m_tiles = (M_TOT + 127) / 128;   // 2055

    qkv_gemm_kernel<<<dim3(3, m_tiles), 256>>>(x, det, inter, W_qkv, b_qkv);
    win_attn_kernel<<<dim3(NH_, NWIN, B_SZ), 256>>>(mask, rel_tab, rel_idx);
    tok_attn_kernel<<<dim3(NH_, B_SZ, 2), 128>>>();
    proj_gemm_kernel<<<dim3(1, m_tiles), 256>>>(W_proj, b_proj, out);
}

// round 5
// speedup vs baseline: 1.2992x; 1.2992x over previous
#include <cuda_runtime.h>
#include <cuda_bf16.h>
#include <cstdint>
#include <cstddef>

// ---------------------------------------------------------------------------
// Problem constants
// ---------------------------------------------------------------------------
#define B_SZ   4
#define NH_    4
#define HD_    32
#define C_DIM  128
#define WS_    8
#define L_WIN  64
#define NWIN   1024        // windows per batch image (32 x 32)
#define N_IMG  65536       // 256*256
#define TD_    100
#define T_TOT  65736       // 65536 + 100 + 100
#define M_TOT  (B_SZ * T_TOT)   // 262944 rows total
#define SCALE_ 0.17677669529663687f   // 32^-0.5

// Scratch (device globals -- no allocation allowed in kernel_launch)
__device__ float g_qkv[(size_t)M_TOT * 384];   // [row][3*C]
__device__ float g_ctx[(size_t)M_TOT * 128];   // attention outputs, proj input

// ---------------------------------------------------------------------------
// Row pointer for the concatenated token matrix [x | det | inter] per batch
// ---------------------------------------------------------------------------
__device__ __forceinline__ const float* token_row(int r,
                                                  const float* __restrict__ x,
                                                  const float* __restrict__ det,
                                                  const float* __restrict__ inter)
{
    int b = r / T_TOT;
    int t = r - b * T_TOT;
    if (t < N_IMG)  return x     + ((size_t)b * N_IMG + t) * C_DIM;
    t -= N_IMG;
    if (t < TD_)    return det   + ((size_t)b * TD_   + t) * C_DIM;
    return inter + ((size_t)b * TD_ + (t - TD_)) * C_DIM;
}

// ---------------------------------------------------------------------------
// MMA helpers (bf16 m16n8k16, fp32 accumulate)
// ---------------------------------------------------------------------------
__device__ __forceinline__ void mma_bf16(float c[4], const uint32_t a[4],
                                         uint32_t b0, uint32_t b1)
{
    asm volatile(
        "mma.sync.aligned.m16n8k16.row.col.f32.bf16.bf16.f32 "
        "{%0,%1,%2,%3}, {%4,%5,%6,%7}, {%8,%9}, {%0,%1,%2,%3};\n"
        : "+f"(c[0]), "+f"(c[1]), "+f"(c[2]), "+f"(c[3])
        : "r"(a[0]), "r"(a[1]), "r"(a[2]), "r"(a[3]), "r"(b0), "r"(b1));
}

__device__ __forceinline__ void ldm_x4(uint32_t r[4], const void* p)
{
    uint32_t sa = (uint32_t)__cvta_generic_to_shared(p);
    asm volatile("ldmatrix.sync.aligned.m8n8.x4.shared.b16 {%0,%1,%2,%3}, [%4];"
                 : "=r"(r[0]), "=r"(r[1]), "=r"(r[2]), "=r"(r[3]) : "r"(sa));
}

// ---------------------------------------------------------------------------
// Tensor-core GEMM with bf16 hi/lo split (3 products -> ~fp32-grade accuracy).
//   IS_QKV=true : A = tokens (gathered), W = W_qkv [384x128], out = g_qkv, ld 384
//   IS_QKV=false: A = g_ctx,             W = W_proj [128x128], out = param, ld 128
// Block tile 128x128, K=128 in chunks of 32. 8 warps as 4(M) x 2(N), each
// warp owns 32x64 via 2x8 m16n8k16 tiles.
//
// B operand note: W is stored [n][k] (out-channel rows, k contiguous) which
// IS col-major KxN. So the B fragment comes from a NON-trans ldmatrix whose
// per-matrix row addresses walk n (lane groups select (n-tile, k-half)).
// ---------------------------------------------------------------------------
template<bool IS_QKV>
__global__ __launch_bounds__(256)
void mma_gemm_kernel(const float* __restrict__ x, const float* __restrict__ det,
                     const float* __restrict__ inter,
                     const float* __restrict__ W, const float* __restrict__ bias,
                     float* __restrict__ out_param)
{
    __shared__ __align__(16) __nv_bfloat16 Ah[128][40];
    __shared__ __align__(16) __nv_bfloat16 Al[128][40];
    __shared__ __align__(16) __nv_bfloat16 Bh[128][40];
    __shared__ __align__(16) __nv_bfloat16 Bl[128][40];

    float* outp = IS_QKV ? g_qkv : out_param;
    const int ldo = IS_QKV ? 384 : 128;

    const int m0   = blockIdx.y * 128;
    const int n0   = blockIdx.x * 128;
    const int tid  = threadIdx.x;
    const int lane = tid & 31;
    const int warp = tid >> 5;
    const int mbase = (warp >> 1) * 32;   // warp M offset in tile
    const int nbase = (warp & 1) * 64;    // warp N offset in tile

    float c[2][8][4] = {};

    for (int kk = 0; kk < 128; kk += 32) {
        // ---- fill smem (convert fp32 -> bf16 hi + lo) ----
        #pragma unroll
        for (int it = 0; it < 4; it++) {
            int idx = tid + it * 256;          // 0..1023
            int row = idx >> 3;                // 0..127
            int c4  = (idx & 7) * 4;           // 0..28
            int r = m0 + row;
            float4 av = make_float4(0.f, 0.f, 0.f, 0.f);
            if (r < M_TOT) {
                if (IS_QKV)
                    av = *(const float4*)(token_row(r, x, det, inter) + kk + c4);
                else
                    av = *(const float4*)(g_ctx + (size_t)r * 128 + kk + c4);
            }
            float va[4] = {av.x, av.y, av.z, av.w};
            #pragma unroll
            for (int j = 0; j < 4; j++) {
                __nv_bfloat16 h = __float2bfloat16(va[j]);
                Ah[row][c4 + j] = h;
                Al[row][c4 + j] = __float2bfloat16(va[j] - __bfloat162float(h));
            }
            float4 bv = *(const float4*)(W + (size_t)(n0 + row) * 128 + kk + c4);
            float vb[4] = {bv.x, bv.y, bv.z, bv.w};
            #pragma unroll
            for (int j = 0; j < 4; j++) {
                __nv_bfloat16 h = __float2bfloat16(vb[j]);
                Bh[row][c4 + j] = h;
                Bl[row][c4 + j] = __float2bfloat16(vb[j] - __bfloat162float(h));
            }
        }
        __syncthreads();

        // ---- compute: 2 k-tiles of 16 within the 32-chunk ----
        #pragma unroll
        for (int kt = 0; kt < 32; kt += 16) {
            // A fragments: lanes 0-15 -> rows 0-15 @ k=kt, lanes 16-31 -> rows 0-15 @ k=kt+8
            uint32_t ah[2][4], al[2][4];
            const int arow_in = lane & 15;
            const int acol = kt + ((lane >> 4) << 3);
            #pragma unroll
            for (int mi = 0; mi < 2; mi++) {
                ldm_x4(ah[mi], &Ah[mbase + mi * 16 + arow_in][acol]);
                ldm_x4(al[mi], &Al[mbase + mi * 16 + arow_in][acol]);
            }
            #pragma unroll
            for (int np = 0; np < 4; np++) {
                // NON-trans ldmatrix over n-rows:
                //   matrix0 (lanes  0- 7): n-tile np*2,   k = kt      -> reg 0
                //   matrix1 (lanes  8-15): n-tile np*2,   k = kt + 8  -> reg 1
                //   matrix2 (lanes 16-23): n-tile np*2+1, k = kt      -> reg 2
                //   matrix3 (lanes 24-31): n-tile np*2+1, k = kt + 8  -> reg 3
                int mtx  = lane >> 3;
                int nrow = nbase + (np * 2 + (mtx >> 1)) * 8 + (lane & 7);
                int kcol = kt + (mtx & 1) * 8;
                uint32_t bh[4], bl[4];
                ldm_x4(bh, &Bh[nrow][kcol]);
                ldm_x4(bl, &Bl[nrow][kcol]);
                #pragma unroll
                for (int mi = 0; mi < 2; mi++) {
                    #pragma unroll
                    for (int j = 0; j < 2; j++) {
                        int ni = np * 2 + j;
                        mma_bf16(c[mi][ni], ah[mi], bh[2 * j], bh[2 * j + 1]);
                        mma_bf16(c[mi][ni], ah[mi], bl[2 * j], bl[2 * j + 1]);
                        mma_bf16(c[mi][ni], al[mi], bh[2 * j], bh[2 * j + 1]);
                    }
                }
            }
        }
        __syncthreads();
    }

    // ---- epilogue: add bias, store fp32 ----
    const int g = lane >> 2;      // row within 8
    const int t = lane & 3;       // col pair
    #pragma unroll
    for (int ni = 0; ni < 8; ni++) {
        int col = n0 + nbase + ni * 8 + t * 2;
        float2 bb = *(const float2*)(bias + col);
        #pragma unroll
        for (int mi = 0; mi < 2; mi++) {
            int r0 = m0 + mbase + mi * 16 + g;
            if (r0 < M_TOT) {
                float2 v = make_float2(c[mi][ni][0] + bb.x, c[mi][ni][1] + bb.y);
                *(float2*)(outp + (size_t)r0 * ldo + col) = v;
            }
            int r1 = r0 + 8;
            if (r1 < M_TOT) {
                float2 v = make_float2(c[mi][ni][2] + bb.x, c[mi][ni][3] + bb.y);
                *(float2*)(outp + (size_t)r1 * ldo + col) = v;
            }
        }
    }
}

// ---------------------------------------------------------------------------
// K2: windowed attention. One block per (head, window, batch). 256 threads.
// ---------------------------------------------------------------------------
__global__ void win_attn_kernel(const float* __restrict__ mask,
                                const float* __restrict__ rel_table,
                                const int*   __restrict__ rel_index)
{
    const int h  = blockIdx.x;   // 0..3
    const int w  = blockIdx.y;   // 0..1023 (hy*32 + wx)
    const int b  = blockIdx.z;   // 0..3
    const int hy = w >> 5, wx = w & 31;
    const int tid = threadIdx.x;

    __shared__ __align__(16) float qs[64][36];
    __shared__ __align__(16) float ks[64][36];
    __shared__ __align__(16) float vs[64][36];
    __shared__ __align__(16) float Ss[64][68];

    #pragma unroll
    for (int it = 0; it < 6; it++) {
        int idx = tid + it * 256;        // 0..1535
        int mtx = idx / 512;             // 0=q 1=k 2=v
        int rem = idx - mtx * 512;
        int tok = rem >> 3;              // 0..63 (= i*8 + j)
        int c4  = (rem & 7) * 4;
        int wi = tok >> 3, wj = tok & 7;
        int t = (hy * 8 + wi) * 256 + (wx * 8 + wj);
        size_t base = ((size_t)(b * T_TOT + t)) * 384 + (size_t)mtx * 128 + h * 32;
        float4 v4 = *(const float4*)(g_qkv + base + c4);
        float* dst = (mtx == 0) ? &qs[0][0] : (mtx == 1) ? &ks[0][0] : &vs[0][0];
        *(float4*)(dst + tok * 36 + c4) = v4;
    }
    __syncthreads();

    // --- S = q k^T ---
    {
        const int tr = tid >> 4, tc = tid & 15;
        const int r0 = tr * 4, c0 = tc * 4;
        float acc[4][4] = {};
        #pragma unroll
        for (int d4 = 0; d4 < 8; d4++) {
            float4 qv[4], kv[4];
            #pragma unroll
            for (int i = 0; i < 4; i++) qv[i] = *(const float4*)&qs[r0 + i][d4 * 4];
            #pragma unroll
            for (int j = 0; j < 4; j++) kv[j] = *(const float4*)&ks[c0 + j][d4 * 4];
            #pragma unroll
            for (int i = 0; i < 4; i++)
                #pragma unroll
                for (int j = 0; j < 4; j++)
                    acc[i][j] += qv[i].x * kv[j].x + qv[i].y * kv[j].y
                               + qv[i].z * kv[j].z + qv[i].w * kv[j].w;
        }
        #pragma unroll
        for (int i = 0; i < 4; i++)
            *(float4*)&Ss[r0 + i][c0] =
                make_float4(acc[i][0], acc[i][1], acc[i][2], acc[i][3]);
    }
    __syncthreads();

    // --- softmax rows: 4 threads per row, 16 cols each ---
    {
        const int r   = tid >> 2;
        const int seg = tid & 3;
        const int cb  = seg * 16;
        const float* mrow = mask + ((size_t)w * 64 + r) * 64 + cb;
        const int*   irow = rel_index + r * 64 + cb;
        float sv[16];
        float mx = -1e30f;
        #pragma unroll
        for (int jj = 0; jj < 16; jj++) {
            float s = Ss[r][cb + jj] * SCALE_ + rel_table[irow[jj] * 4 + h] + mrow[jj];
            sv[jj] = s;
            mx = fmaxf(mx, s);
        }
        mx = fmaxf(mx, __shfl_xor_sync(0xffffffffu, mx, 1));
        mx = fmaxf(mx, __shfl_xor_sync(0xffffffffu, mx, 2));
        float sum = 0.f;
        #pragma unroll
        for (int jj = 0; jj < 16; jj++) {
            sv[jj] = __expf(sv[jj] - mx);
            sum += sv[jj];
        }
        sum += __shfl_xor_sync(0xffffffffu, sum, 1);
        sum += __shfl_xor_sync(0xffffffffu, sum, 2);
        float inv = 1.0f / sum;
        #pragma unroll
        for (int jj = 0; jj < 16; jj++)
            Ss[r][cb + jj] = sv[jj] * inv;
    }
    __syncthreads();

    // --- O = P v ---
    {
        const int trr = tid >> 3;
        const int td  = tid & 7;
        float o0[4] = {}, o1[4] = {};
        #pragma unroll 16
        for (int j = 0; j < 64; j++) {
            float p0 = Ss[2 * trr][j];
            float p1 = Ss[2 * trr + 1][j];
            float4 vv = *(const float4*)&vs[j][td * 4];
            o0[0] += p0 * vv.x; o0[1] += p0 * vv.y; o0[2] += p0 * vv.z; o0[3] += p0 * vv.w;
            o1[0] += p1 * vv.x; o1[1] += p1 * vv.y; o1[2] += p1 * vv.z; o1[3] += p1 * vv.w;
        }
        #pragma unroll
        for (int rr = 0; rr < 2; rr++) {
            int l = 2 * trr + rr;
            int wi = l >> 3, wj = l & 7;
            int t = (hy * 8 + wi) * 256 + (wx * 8 + wj);
            float* op = g_ctx + ((size_t)(b * T_TOT + t)) * 128 + h * 32 + td * 4;
            const float* src = rr ? o1 : o0;
            *(float4*)op = make_float4(src[0], src[1], src[2], src[3]);
        }
    }
}

// ---------------------------------------------------------------------------
// K3: det/inter token MHA. One block per (head, batch, type). 128 threads.
// ---------------------------------------------------------------------------
__global__ void tok_attn_kernel()
{
    const int h  = blockIdx.x;
    const int b  = blockIdx.y;
    const int ty = blockIdx.z;           // 0 = det, 1 = inter
    const int tid = threadIdx.x;
    const int tbase = N_IMG + ty * TD_;

    __shared__ __align__(16) float ks[100][32];
    __shared__ __align__(16) float vs[100][32];

    for (int idx = tid; idx < 100 * 8; idx += 128) {
        int tok = idx >> 3;
        int c4  = (idx & 7) * 4;
        size_t base = ((size_t)(b * T_TOT + tbase + tok)) * 384 + h * 32;
        *(float4*)&ks[tok][c4] = *(const float4*)(g_qkv + base + 128 + c4);
        *(float4*)&vs[tok][c4] = *(const float4*)(g_qkv + base + 256 + c4);
    }
    __syncthreads();

    if (tid < 100) {
        const int r = tid;
        float q[32];
        const float* qp = g_qkv + ((size_t)(b * T_TOT + tbase + r)) * 384 + h * 32;
        #pragma unroll
        for (int d = 0; d < 32; d++) q[d] = qp[d] * SCALE_;

        float srow[100];
        float mx = -1e30f;
        for (int j = 0; j < 100; j++) {
            float s = 0.f;
            #pragma unroll
            for (int d = 0; d < 32; d++) s += q[d] * ks[j][d];
            srow[j] = s;
            mx = fmaxf(mx, s);
        }
        float sum = 0.f;
        for (int j = 0; j < 100; j++) {
            srow[j] = __expf(srow[j] - mx);
            sum += srow[j];
        }
        float inv = 1.0f / sum;
        float o[32] = {};
        for (int j = 0; j < 100; j++) {
            float p = srow[j] * inv;
            #pragma unroll
            for (int d = 0; d < 32; d++) o[d] += p * vs[j][d];
        }
        float* op = g_ctx + ((size_t)(b * T_TOT + tbase + r)) * 128 + h * 32;
        #pragma unroll
        for (int d = 0; d < 32; d++) op[d] = o[d];
    }
}

// ---------------------------------------------------------------------------
// kernel_launch
// Inputs (metadata order): x, det, inter, mask, W_qkv, b_qkv, W_proj, b_proj,
//                          rel_table, rel_index
// ---------------------------------------------------------------------------
extern "C" void kernel_launch(void* const* d_in, const int* in_sizes, int n_in,
                              void* d_out, int out_size)
{
    (void)in_sizes; (void)n_in; (void)out_size;
    const float* x        = (const float*)d_in[0];
    const float* det      = (const float*)d_in[1];
    const float* inter    = (const float*)d_in[2];
    const float* mask     = (const float*)d_in[3];
    const float* W_qkv    = (const float*)d_in[4];
    const float* b_qkv    = (const float*)d_in[5];
    const float* W_proj   = (const float*)d_in[6];
    const float* b_proj   = (const float*)d_in[7];
    const float* rel_tab  = (const float*)d_in[8];
    const int*   rel_idx  = (const int*)d_in[9];
    float* out = (float*)d_out;

    const int m_tiles = (M_TOT + 127) / 128;   // 2055

    mma_gemm_kernel<true><<<dim3(3, m_tiles), 256>>>(x, det, inter,
                                                     W_qkv, b_qkv, nullptr);
    win_attn_kernel<<<dim3(NH_, NWIN, B_SZ), 256>>>(mask, rel_tab, rel_idx);
    tok_attn_kernel<<<dim3(NH_, B_SZ, 2), 128>>>();
    mma_gemm_kernel<false><<<dim3(1, m_tiles), 256>>>(nullptr, nullptr, nullptr,
                                                      W_proj, b_proj, out);
}

// round 6
// speedup vs baseline: 2.3385x; 1.8000x over previous
#include <cuda_runtime.h>
#include <cuda_bf16.h>
#include <cstdint>
#include <cstddef>

// ---------------------------------------------------------------------------
// Problem constants
// ---------------------------------------------------------------------------
#define B_SZ   4
#define NH_    4
#define HD_    32
#define C_DIM  128
#define WS_    8
#define L_WIN  64
#define NWIN   1024        // windows per batch image (32 x 32)
#define N_IMG  65536       // 256*256
#define TD_    100
#define T_TOT  65736       // 65536 + 100 + 100
#define M_TOT  (B_SZ * T_TOT)   // 262944 rows total
#define SCALE_ 0.17677669529663687f   // 32^-0.5

// Scratch (device globals -- no allocation allowed in kernel_launch)
__device__ float g_qkv[(size_t)M_TOT * 384];   // [row][3*C]
__device__ float g_ctx[(size_t)M_TOT * 128];   // attention outputs, proj input
__device__ float g_bias[NH_ * L_WIN * L_WIN];  // pregathered rel-pos bias per head

// ---------------------------------------------------------------------------
// Row pointer for the concatenated token matrix [x | det | inter] per batch
// ---------------------------------------------------------------------------
__device__ __forceinline__ const float* token_row(int r,
                                                  const float* __restrict__ x,
                                                  const float* __restrict__ det,
                                                  const float* __restrict__ inter)
{
    int b = r / T_TOT;
    int t = r - b * T_TOT;
    if (t < N_IMG)  return x     + ((size_t)b * N_IMG + t) * C_DIM;
    t -= N_IMG;
    if (t < TD_)    return det   + ((size_t)b * TD_   + t) * C_DIM;
    return inter + ((size_t)b * TD_ + (t - TD_)) * C_DIM;
}

// ---------------------------------------------------------------------------
// MMA helpers (bf16 m16n8k16, fp32 accumulate)
// ---------------------------------------------------------------------------
__device__ __forceinline__ void mma_bf16(float c[4], const uint32_t a[4],
                                         uint32_t b0, uint32_t b1)
{
    asm volatile(
        "mma.sync.aligned.m16n8k16.row.col.f32.bf16.bf16.f32 "
        "{%0,%1,%2,%3}, {%4,%5,%6,%7}, {%8,%9}, {%0,%1,%2,%3};\n"
        : "+f"(c[0]), "+f"(c[1]), "+f"(c[2]), "+f"(c[3])
        : "r"(a[0]), "r"(a[1]), "r"(a[2]), "r"(a[3]), "r"(b0), "r"(b1));
}

__device__ __forceinline__ void ldm_x4(uint32_t r[4], const void* p)
{
    uint32_t sa = (uint32_t)__cvta_generic_to_shared(p);
    asm volatile("ldmatrix.sync.aligned.m8n8.x4.shared.b16 {%0,%1,%2,%3}, [%4];"
                 : "=r"(r[0]), "=r"(r[1]), "=r"(r[2]), "=r"(r[3]) : "r"(sa));
}

__device__ __forceinline__ void ldm_x4_t(uint32_t r[4], const void* p)
{
    uint32_t sa = (uint32_t)__cvta_generic_to_shared(p);
    asm volatile("ldmatrix.sync.aligned.m8n8.x4.trans.shared.b16 {%0,%1,%2,%3}, [%4];"
                 : "=r"(r[0]), "=r"(r[1]), "=r"(r[2]), "=r"(r[3]) : "r"(sa));
}

// pack two fp32 into bf16x2: low half = e0, high half = e1
__device__ __forceinline__ uint32_t pack_bf16x2(float e0, float e1)
{
    uint32_t r;
    asm("cvt.rn.bf16x2.f32 %0, %1, %2;" : "=r"(r) : "f"(e1), "f"(e0));
    return r;
}

// ---------------------------------------------------------------------------
// K0: pregather the relative-position bias per head: g_bias[h][r*64+c]
// ---------------------------------------------------------------------------
__global__ void bias_gather_kernel(const float* __restrict__ rel_table,
                                   const int*   __restrict__ rel_index)
{
    int idx = blockIdx.x * 256 + threadIdx.x;   // 0..4095
    if (idx < L_WIN * L_WIN) {
        int ri = rel_index[idx];
        #pragma unroll
        for (int h = 0; h < NH_; h++)
            g_bias[h * (L_WIN * L_WIN) + idx] = rel_table[ri * NH_ + h];
    }
}

// ---------------------------------------------------------------------------
// Tensor-core GEMM with bf16 hi/lo split (3 products -> ~fp32-grade accuracy).
// ---------------------------------------------------------------------------
template<bool IS_QKV>
__global__ __launch_bounds__(256)
void mma_gemm_kernel(const float* __restrict__ x, const float* __restrict__ det,
                     const float* __restrict__ inter,
                     const float* __restrict__ W, const float* __restrict__ bias,
                     float* __restrict__ out_param)
{
    __shared__ __align__(16) __nv_bfloat16 Ah[128][40];
    __shared__ __align__(16) __nv_bfloat16 Al[128][40];
    __shared__ __align__(16) __nv_bfloat16 Bh[128][40];
    __shared__ __align__(16) __nv_bfloat16 Bl[128][40];

    float* outp = IS_QKV ? g_qkv : out_param;
    const int ldo = IS_QKV ? 384 : 128;

    const int m0   = blockIdx.y * 128;
    const int n0   = blockIdx.x * 128;
    const int tid  = threadIdx.x;
    const int lane = tid & 31;
    const int warp = tid >> 5;
    const int mbase = (warp >> 1) * 32;
    const int nbase = (warp & 1) * 64;

    float c[2][8][4] = {};

    for (int kk = 0; kk < 128; kk += 32) {
        #pragma unroll
        for (int it = 0; it < 4; it++) {
            int idx = tid + it * 256;
            int row = idx >> 3;
            int c4  = (idx & 7) * 4;
            int r = m0 + row;
            float4 av = make_float4(0.f, 0.f, 0.f, 0.f);
            if (r < M_TOT) {
                if (IS_QKV)
                    av = *(const float4*)(token_row(r, x, det, inter) + kk + c4);
                else
                    av = *(const float4*)(g_ctx + (size_t)r * 128 + kk + c4);
            }
            float va[4] = {av.x, av.y, av.z, av.w};
            #pragma unroll
            for (int j = 0; j < 4; j++) {
                __nv_bfloat16 h = __float2bfloat16(va[j]);
                Ah[row][c4 + j] = h;
                Al[row][c4 + j] = __float2bfloat16(va[j] - __bfloat162float(h));
            }
            float4 bv = *(const float4*)(W + (size_t)(n0 + row) * 128 + kk + c4);
            float vb[4] = {bv.x, bv.y, bv.z, bv.w};
            #pragma unroll
            for (int j = 0; j < 4; j++) {
                __nv_bfloat16 h = __float2bfloat16(vb[j]);
                Bh[row][c4 + j] = h;
                Bl[row][c4 + j] = __float2bfloat16(vb[j] - __bfloat162float(h));
            }
        }
        __syncthreads();

        #pragma unroll
        for (int kt = 0; kt < 32; kt += 16) {
            uint32_t ah[2][4], al[2][4];
            const int arow_in = lane & 15;
            const int acol = kt + ((lane >> 4) << 3);
            #pragma unroll
            for (int mi = 0; mi < 2; mi++) {
                ldm_x4(ah[mi], &Ah[mbase + mi * 16 + arow_in][acol]);
                ldm_x4(al[mi], &Al[mbase + mi * 16 + arow_in][acol]);
            }
            #pragma unroll
            for (int np = 0; np < 4; np++) {
                int mtx  = lane >> 3;
                int nrow = nbase + (np * 2 + (mtx >> 1)) * 8 + (lane & 7);
                int kcol = kt + (mtx & 1) * 8;
                uint32_t bh[4], bl[4];
                ldm_x4(bh, &Bh[nrow][kcol]);
                ldm_x4(bl, &Bl[nrow][kcol]);
                #pragma unroll
                for (int mi = 0; mi < 2; mi++) {
                    #pragma unroll
                    for (int j = 0; j < 2; j++) {
                        int ni = np * 2 + j;
                        mma_bf16(c[mi][ni], ah[mi], bh[2 * j], bh[2 * j + 1]);
                        mma_bf16(c[mi][ni], ah[mi], bl[2 * j], bl[2 * j + 1]);
                        mma_bf16(c[mi][ni], al[mi], bh[2 * j], bh[2 * j + 1]);
                    }
                }
            }
        }
        __syncthreads();
    }

    const int g = lane >> 2;
    const int t = lane & 3;
    #pragma unroll
    for (int ni = 0; ni < 8; ni++) {
        int col = n0 + nbase + ni * 8 + t * 2;
        float2 bb = *(const float2*)(bias + col);
        #pragma unroll
        for (int mi = 0; mi < 2; mi++) {
            int r0 = m0 + mbase + mi * 16 + g;
            if (r0 < M_TOT) {
                float2 v = make_float2(c[mi][ni][0] + bb.x, c[mi][ni][1] + bb.y);
                *(float2*)(outp + (size_t)r0 * ldo + col) = v;
            }
            int r1 = r0 + 8;
            if (r1 < M_TOT) {
                float2 v = make_float2(c[mi][ni][2] + bb.x, c[mi][ni][3] + bb.y);
                *(float2*)(outp + (size_t)r1 * ldo + col) = v;
            }
        }
    }
}

// ---------------------------------------------------------------------------
// K2: windowed attention, tensor-core version.
// Block = (head, window, batch), 128 threads (4 warps), warp owns 16 rows.
// S = QK^T (bf16 hi/lo, 3 mma), softmax in accumulator layout,
// P repacked in registers as A-fragments, O = PV (bf16 hi/lo, 3 mma).
// ---------------------------------------------------------------------------
__global__ __launch_bounds__(128)
void win_attn_mma_kernel(const float* __restrict__ mask)
{
    const int h  = blockIdx.x;
    const int w  = blockIdx.y;
    const int b  = blockIdx.z;
    const int hy = w >> 5, wx = w & 31;
    const int tid  = threadIdx.x;
    const int lane = tid & 31;
    const int warp = tid >> 5;

    __shared__ __align__(16) __nv_bfloat16 qh[64][40], ql[64][40];
    __shared__ __align__(16) __nv_bfloat16 kh[64][40], kl[64][40];
    __shared__ __align__(16) __nv_bfloat16 vh[64][40], vl[64][40];
    __shared__ __align__(16) float Badd[64][66];

    // ---- load q,k,v (fp32 -> bf16 hi/lo) ----
    #pragma unroll
    for (int it = 0; it < 12; it++) {
        int idx = tid + it * 128;        // 0..1535 float4 slots
        int mtx = idx / 512;             // 0=q 1=k 2=v
        int rem = idx - mtx * 512;
        int tok = rem >> 3;
        int c4  = (rem & 7) * 4;
        int wi = tok >> 3, wj = tok & 7;
        int t = (hy * 8 + wi) * 256 + (wx * 8 + wj);
        size_t base = ((size_t)(b * T_TOT + t)) * 384 + (size_t)mtx * 128 + h * 32;
        float4 v4 = *(const float4*)(g_qkv + base + c4);
        float vv[4] = {v4.x, v4.y, v4.z, v4.w};
        __nv_bfloat16* dh = (mtx == 0) ? &qh[0][0] : (mtx == 1) ? &kh[0][0] : &vh[0][0];
        __nv_bfloat16* dl = (mtx == 0) ? &ql[0][0] : (mtx == 1) ? &kl[0][0] : &vl[0][0];
        #pragma unroll
        for (int j = 0; j < 4; j++) {
            __nv_bfloat16 hi = __float2bfloat16(vv[j]);
            dh[tok * 40 + c4 + j] = hi;
            dl[tok * 40 + c4 + j] = __float2bfloat16(vv[j] - __bfloat162float(hi));
        }
    }
    // ---- stage bias + mask ----
    {
        const float* gb = g_bias + h * (L_WIN * L_WIN);
        const float* mk = mask + (size_t)w * (L_WIN * L_WIN);
        #pragma unroll
        for (int it = 0; it < 32; it++) {
            int idx = tid + it * 128;    // 0..4095
            Badd[idx >> 6][idx & 63] = gb[idx] + mk[idx];
        }
    }
    __syncthreads();

    // ---- S = Q K^T : warp rows [warp*16, warp*16+16), 8 n-tiles ----
    const int mrow = warp * 16;
    float sc[8][4] = {};
    #pragma unroll
    for (int kt = 0; kt < 32; kt += 16) {
        uint32_t ah[4], al[4];
        const int arow = mrow + (lane & 15);
        const int acol = kt + ((lane >> 4) << 3);
        ldm_x4(ah, &qh[arow][acol]);
        ldm_x4(al, &ql[arow][acol]);
        #pragma unroll
        for (int np = 0; np < 4; np++) {
            int mtx  = lane >> 3;
            int nrow = (np * 2 + (mtx >> 1)) * 8 + (lane & 7);
            int kcol = kt + (mtx & 1) * 8;
            uint32_t bh[4], bl[4];
            ldm_x4(bh, &kh[nrow][kcol]);
            ldm_x4(bl, &kl[nrow][kcol]);
            #pragma unroll
            for (int j = 0; j < 2; j++) {
                int ni = np * 2 + j;
                mma_bf16(sc[ni], ah, bh[2 * j], bh[2 * j + 1]);
                mma_bf16(sc[ni], ah, bl[2 * j], bl[2 * j + 1]);
                mma_bf16(sc[ni], al, bh[2 * j], bh[2 * j + 1]);
            }
        }
    }

    // ---- softmax in accumulator layout ----
    const int g = lane >> 2;      // row within 8-group
    const int t = lane & 3;       // col pair
    const int r0 = mrow + g;      // rows r0 (c0,c1) and r0+8 (c2,c3)
    float mx0 = -1e30f, mx1 = -1e30f;
    #pragma unroll
    for (int j = 0; j < 8; j++) {
        int cbase = j * 8 + t * 2;
        sc[j][0] = sc[j][0] * SCALE_ + Badd[r0][cbase];
        sc[j][1] = sc[j][1] * SCALE_ + Badd[r0][cbase + 1];
        sc[j][2] = sc[j][2] * SCALE_ + Badd[r0 + 8][cbase];
        sc[j][3] = sc[j][3] * SCALE_ + Badd[r0 + 8][cbase + 1];
        mx0 = fmaxf(mx0, fmaxf(sc[j][0], sc[j][1]));
        mx1 = fmaxf(mx1, fmaxf(sc[j][2], sc[j][3]));
    }
    mx0 = fmaxf(mx0, __shfl_xor_sync(0xffffffffu, mx0, 1));
    mx0 = fmaxf(mx0, __shfl_xor_sync(0xffffffffu, mx0, 2));
    mx1 = fmaxf(mx1, __shfl_xor_sync(0xffffffffu, mx1, 1));
    mx1 = fmaxf(mx1, __shfl_xor_sync(0xffffffffu, mx1, 2));
    float sum0 = 0.f, sum1 = 0.f;
    #pragma unroll
    for (int j = 0; j < 8; j++) {
        sc[j][0] = __expf(sc[j][0] - mx0); sum0 += sc[j][0];
        sc[j][1] = __expf(sc[j][1] - mx0); sum0 += sc[j][1];
        sc[j][2] = __expf(sc[j][2] - mx1); sum1 += sc[j][2];
        sc[j][3] = __expf(sc[j][3] - mx1); sum1 += sc[j][3];
    }
    sum0 += __shfl_xor_sync(0xffffffffu, sum0, 1);
    sum0 += __shfl_xor_sync(0xffffffffu, sum0, 2);
    sum1 += __shfl_xor_sync(0xffffffffu, sum1, 1);
    sum1 += __shfl_xor_sync(0xffffffffu, sum1, 2);
    const float inv0 = 1.0f / sum0, inv1 = 1.0f / sum1;
    #pragma unroll
    for (int j = 0; j < 8; j++) {
        sc[j][0] *= inv0; sc[j][1] *= inv0;
        sc[j][2] *= inv1; sc[j][3] *= inv1;
    }

    // ---- repack P (C-fragments) -> A-fragments, hi/lo split ----
    uint32_t pah[4][4], pal[4][4];
    #pragma unroll
    for (int kt2 = 0; kt2 < 4; kt2++) {
        #pragma unroll
        for (int half = 0; half < 2; half++) {     // n-tile 2kt2 + half
            const float* cc = sc[2 * kt2 + half];
            float h0 = __bfloat162float(__float2bfloat16(cc[0]));
            float h1 = __bfloat162float(__float2bfloat16(cc[1]));
            float h2 = __bfloat162float(__float2bfloat16(cc[2]));
            float h3 = __bfloat162float(__float2bfloat16(cc[3]));
            pah[kt2][half * 2 + 0] = pack_bf16x2(h0, h1);            // row g
            pah[kt2][half * 2 + 1] = pack_bf16x2(h2, h3);            // row g+8
            pal[kt2][half * 2 + 0] = pack_bf16x2(cc[0] - h0, cc[1] - h1);
            pal[kt2][half * 2 + 1] = pack_bf16x2(cc[2] - h2, cc[3] - h3);
        }
    }
    // A-frag register order for m16n8k16: a0=(row g,k lo8) a1=(row g+8,k lo8)
    // a2=(row g,k hi8) a3=(row g+8,k hi8) -- our pack above already matches:
    // index 0: n-tile even (k 0-7 within 16) rows g / index1 rows g+8,
    // index 2/3: n-tile odd (k 8-15).

    // ---- O = P V : 4 k-tiles (tokens), 4 n-tiles (dims) ----
    float oc[4][4] = {};
    #pragma unroll
    for (int kt2 = 0; kt2 < 4; kt2++) {
        #pragma unroll
        for (int half = 0; half < 2; half++) {      // dims 0-15 / 16-31
            int mtx = lane >> 3;
            int vrow = kt2 * 16 + (mtx & 1) * 8 + (lane & 7);
            int vcol = half * 16 + (mtx >> 1) * 8;
            uint32_t bh[4], bl[4];
            ldm_x4_t(bh, &vh[vrow][vcol]);
            ldm_x4_t(bl, &vl[vrow][vcol]);
            #pragma unroll
            for (int j = 0; j < 2; j++) {
                int ni = half * 2 + j;
                mma_bf16(oc[ni], pah[kt2], bh[2 * j], bh[2 * j + 1]);
                mma_bf16(oc[ni], pah[kt2], bl[2 * j], bl[2 * j + 1]);
                mma_bf16(oc[ni], pal[kt2], bh[2 * j], bh[2 * j + 1]);
            }
        }
    }

    // ---- store O ----
    #pragma unroll
    for (int rr = 0; rr < 2; rr++) {
        int l = r0 + rr * 8;                 // window row
        int wi = l >> 3, wj = l & 7;
        int tk = (hy * 8 + wi) * 256 + (wx * 8 + wj);
        float* op = g_ctx + ((size_t)(b * T_TOT + tk)) * 128 + h * 32;
        #pragma unroll
        for (int ni = 0; ni < 4; ni++) {
            float2 v = rr ? make_float2(oc[ni][2], oc[ni][3])
                          : make_float2(oc[ni][0], oc[ni][1]);
            *(float2*)(op + ni * 8 + t * 2) = v;
        }
    }
}

// ---------------------------------------------------------------------------
// K3: det/inter token MHA. One block per (head, batch, type). 128 threads.
// ---------------------------------------------------------------------------
__global__ void tok_attn_kernel()
{
    const int h  = blockIdx.x;
    const int b  = blockIdx.y;
    const int ty = blockIdx.z;
    const int tid = threadIdx.x;
    const int tbase = N_IMG + ty * TD_;

    __shared__ __align__(16) float ks[100][32];
    __shared__ __align__(16) float vs[100][32];

    for (int idx = tid; idx < 100 * 8; idx += 128) {
        int tok = idx >> 3;
        int c4  = (idx & 7) * 4;
        size_t base = ((size_t)(b * T_TOT + tbase + tok)) * 384 + h * 32;
        *(float4*)&ks[tok][c4] = *(const float4*)(g_qkv + base + 128 + c4);
        *(float4*)&vs[tok][c4] = *(const float4*)(g_qkv + base + 256 + c4);
    }
    __syncthreads();

    if (tid < 100) {
        const int r = tid;
        float q[32];
        const float* qp = g_qkv + ((size_t)(b * T_TOT + tbase + r)) * 384 + h * 32;
        #pragma unroll
        for (int d = 0; d < 32; d++) q[d] = qp[d] * SCALE_;

        float srow[100];
        float mx = -1e30f;
        for (int j = 0; j < 100; j++) {
            float s = 0.f;
            #pragma unroll
            for (int d = 0; d < 32; d++) s += q[d] * ks[j][d];
            srow[j] = s;
            mx = fmaxf(mx, s);
        }
        float sum = 0.f;
        for (int j = 0; j < 100; j++) {
            srow[j] = __expf(srow[j] - mx);
            sum += srow[j];
        }
        float inv = 1.0f / sum;
        float o[32] = {};
        for (int j = 0; j < 100; j++) {
            float p = srow[j] * inv;
            #pragma unroll
            for (int d = 0; d < 32; d++) o[d] += p * vs[j][d];
        }
        float* op = g_ctx + ((size_t)(b * T_TOT + tbase + r)) * 128 + h * 32;
        #pragma unroll
        for (int d = 0; d < 32; d++) op[d] = o[d];
    }
}

// ---------------------------------------------------------------------------
// kernel_launch
// ---------------------------------------------------------------------------
extern "C" void kernel_launch(void* const* d_in, const int* in_sizes, int n_in,
                              void* d_out, int out_size)
{
    (void)in_sizes; (void)n_in; (void)out_size;
    const float* x        = (const float*)d_in[0];
    const float* det      = (const float*)d_in[1];
    const float* inter    = (const float*)d_in[2];
    const float* mask     = (const float*)d_in[3];
    const float* W_qkv    = (const float*)d_in[4];
    const float* b_qkv    = (const float*)d_in[5];
    const float* W_proj   = (const float*)d_in[6];
    const float* b_proj   = (const float*)d_in[7];
    const float* rel_tab  = (const float*)d_in[8];
    const int*   rel_idx  = (const int*)d_in[9];
    float* out = (float*)d_out;

    const int m_tiles = (M_TOT + 127) / 128;   // 2055

    bias_gather_kernel<<<16, 256>>>(rel_tab, rel_idx);
    mma_gemm_kernel<true><<<dim3(3, m_tiles), 256>>>(x, det, inter,
                                                     W_qkv, b_qkv, nullptr);
    win_attn_mma_kernel<<<dim3(NH_, NWIN, B_SZ), 128>>>(mask);
    tok_attn_kernel<<<dim3(NH_, B_SZ, 2), 128>>>();
    mma_gemm_kernel<false><<<dim3(1, m_tiles), 256>>>(nullptr, nullptr, nullptr,
                                                      W_proj, b_proj, out);
}

// round 7
// speedup vs baseline: 2.4747x; 1.0582x over previous
#include <cuda_runtime.h>
#include <cuda_bf16.h>
#include <cstdint>
#include <cstddef>

// ---------------------------------------------------------------------------
// Problem constants
// ---------------------------------------------------------------------------
#define B_SZ   4
#define NH_    4
#define HD_    32
#define C_DIM  128
#define WS_    8
#define L_WIN  64
#define NWIN   1024        // windows per batch image (32 x 32)
#define N_IMG  65536       // 256*256
#define TD_    100
#define T_TOT  65736       // 65536 + 100 + 100
#define M_TOT  (B_SZ * T_TOT)   // 262944 rows total
#define SCALE_ 0.17677669529663687f   // 32^-0.5

// Scratch (device globals -- no allocation allowed in kernel_launch)
__device__ float g_qkv[(size_t)M_TOT * 384];   // [row][3*C]
__device__ float g_ctx[(size_t)M_TOT * 128];   // attention outputs, proj input
__device__ float g_bias[NH_ * L_WIN * L_WIN];  // pregathered rel-pos bias per head

// ---------------------------------------------------------------------------
// Row pointer for the concatenated token matrix [x | det | inter] per batch
// ---------------------------------------------------------------------------
__device__ __forceinline__ const float* token_row(int r,
                                                  const float* __restrict__ x,
                                                  const float* __restrict__ det,
                                                  const float* __restrict__ inter)
{
    int b = r / T_TOT;
    int t = r - b * T_TOT;
    if (t < N_IMG)  return x     + ((size_t)b * N_IMG + t) * C_DIM;
    t -= N_IMG;
    if (t < TD_)    return det   + ((size_t)b * TD_   + t) * C_DIM;
    return inter + ((size_t)b * TD_ + (t - TD_)) * C_DIM;
}

// ---------------------------------------------------------------------------
// MMA helpers (bf16 m16n8k16, fp32 accumulate)
// ---------------------------------------------------------------------------
__device__ __forceinline__ void mma_bf16(float c[4], const uint32_t a[4],
                                         uint32_t b0, uint32_t b1)
{
    asm volatile(
        "mma.sync.aligned.m16n8k16.row.col.f32.bf16.bf16.f32 "
        "{%0,%1,%2,%3}, {%4,%5,%6,%7}, {%8,%9}, {%0,%1,%2,%3};\n"
        : "+f"(c[0]), "+f"(c[1]), "+f"(c[2]), "+f"(c[3])
        : "r"(a[0]), "r"(a[1]), "r"(a[2]), "r"(a[3]), "r"(b0), "r"(b1));
}

__device__ __forceinline__ void ldm_x4(uint32_t r[4], const void* p)
{
    uint32_t sa = (uint32_t)__cvta_generic_to_shared(p);
    asm volatile("ldmatrix.sync.aligned.m8n8.x4.shared.b16 {%0,%1,%2,%3}, [%4];"
                 : "=r"(r[0]), "=r"(r[1]), "=r"(r[2]), "=r"(r[3]) : "r"(sa));
}

__device__ __forceinline__ void ldm_x4_t(uint32_t r[4], const void* p)
{
    uint32_t sa = (uint32_t)__cvta_generic_to_shared(p);
    asm volatile("ldmatrix.sync.aligned.m8n8.x4.trans.shared.b16 {%0,%1,%2,%3}, [%4];"
                 : "=r"(r[0]), "=r"(r[1]), "=r"(r[2]), "=r"(r[3]) : "r"(sa));
}

// pack two fp32 into bf16x2: low half = e0, high half = e1
__device__ __forceinline__ uint32_t pack_bf16x2(float e0, float e1)
{
    uint32_t r;
    asm("cvt.rn.bf16x2.f32 %0, %1, %2;" : "=r"(r) : "f"(e1), "f"(e0));
    return r;
}

// ---------------------------------------------------------------------------
// K0: pregather the relative-position bias per head: g_bias[h][r*64+c]
// ---------------------------------------------------------------------------
__global__ void bias_gather_kernel(const float* __restrict__ rel_table,
                                   const int*   __restrict__ rel_index)
{
    int idx = blockIdx.x * 256 + threadIdx.x;   // 0..4095
    if (idx < L_WIN * L_WIN) {
        int ri = rel_index[idx];
        #pragma unroll
        for (int h = 0; h < NH_; h++)
            g_bias[h * (L_WIN * L_WIN) + idx] = rel_table[ri * NH_ + h];
    }
}

// ---------------------------------------------------------------------------
// Tensor-core GEMM with bf16 hi/lo split (3 products -> ~fp32-grade accuracy).
// Register-prefetch pipeline: next chunk's global loads are issued right
// after the smem store of the current chunk, and retire under the mma block.
// ---------------------------------------------------------------------------
template<bool IS_QKV>
__global__ __launch_bounds__(256, 2)
void mma_gemm_kernel(const float* __restrict__ x, const float* __restrict__ det,
                     const float* __restrict__ inter,
                     const float* __restrict__ W, const float* __restrict__ bias,
                     float* __restrict__ out_param)
{
    __shared__ __align__(16) __nv_bfloat16 Ah[128][40];
    __shared__ __align__(16) __nv_bfloat16 Al[128][40];
    __shared__ __align__(16) __nv_bfloat16 Bh[128][40];
    __shared__ __align__(16) __nv_bfloat16 Bl[128][40];

    float* outp = IS_QKV ? g_qkv : out_param;
    const int ldo = IS_QKV ? 384 : 128;

    const int m0   = blockIdx.y * 128;
    const int n0   = blockIdx.x * 128;
    const int tid  = threadIdx.x;
    const int lane = tid & 31;
    const int warp = tid >> 5;
    const int mbase = (warp >> 1) * 32;
    const int nbase = (warp & 1) * 64;

    float c[2][8][4] = {};
    float4 pa[4], pb[4];

    // prologue: load chunk 0
    #pragma unroll
    for (int it = 0; it < 4; it++) {
        int idx = tid + it * 256;
        int row = idx >> 3;
        int c4  = (idx & 7) * 4;
        int r = m0 + row;
        pa[it] = make_float4(0.f, 0.f, 0.f, 0.f);
        if (r < M_TOT) {
            if (IS_QKV) pa[it] = *(const float4*)(token_row(r, x, det, inter) + c4);
            else        pa[it] = *(const float4*)(g_ctx + (size_t)r * 128 + c4);
        }
        pb[it] = *(const float4*)(W + (size_t)(n0 + row) * 128 + c4);
    }

    #pragma unroll
    for (int kc = 0; kc < 4; kc++) {
        // ---- store staged regs -> smem (convert fp32 -> bf16 hi + lo) ----
        #pragma unroll
        for (int it = 0; it < 4; it++) {
            int idx = tid + it * 256;
            int row = idx >> 3;
            int c4  = (idx & 7) * 4;
            float va[4] = {pa[it].x, pa[it].y, pa[it].z, pa[it].w};
            #pragma unroll
            for (int j = 0; j < 4; j++) {
                __nv_bfloat16 h = __float2bfloat16(va[j]);
                Ah[row][c4 + j] = h;
                Al[row][c4 + j] = __float2bfloat16(va[j] - __bfloat162float(h));
            }
            float vb[4] = {pb[it].x, pb[it].y, pb[it].z, pb[it].w};
            #pragma unroll
            for (int j = 0; j < 4; j++) {
                __nv_bfloat16 h = __float2bfloat16(vb[j]);
                Bh[row][c4 + j] = h;
                Bl[row][c4 + j] = __float2bfloat16(vb[j] - __bfloat162float(h));
            }
        }
        __syncthreads();

        // ---- prefetch next chunk (retires under the mma block below) ----
        if (kc < 3) {
            int kk = (kc + 1) * 32;
            #pragma unroll
            for (int it = 0; it < 4; it++) {
                int idx = tid + it * 256;
                int row = idx >> 3;
                int c4  = (idx & 7) * 4;
                int r = m0 + row;
                pa[it] = make_float4(0.f, 0.f, 0.f, 0.f);
                if (r < M_TOT) {
                    if (IS_QKV) pa[it] = *(const float4*)(token_row(r, x, det, inter) + kk + c4);
                    else        pa[it] = *(const float4*)(g_ctx + (size_t)r * 128 + kk + c4);
                }
                pb[it] = *(const float4*)(W + (size_t)(n0 + row) * 128 + kk + c4);
            }
        }

        // ---- compute on current smem chunk ----
        #pragma unroll
        for (int kt = 0; kt < 32; kt += 16) {
            uint32_t ah[2][4], al[2][4];
            const int arow_in = lane & 15;
            const int acol = kt + ((lane >> 4) << 3);
            #pragma unroll
            for (int mi = 0; mi < 2; mi++) {
                ldm_x4(ah[mi], &Ah[mbase + mi * 16 + arow_in][acol]);
                ldm_x4(al[mi], &Al[mbase + mi * 16 + arow_in][acol]);
            }
            #pragma unroll
            for (int np = 0; np < 4; np++) {
                int mtx  = lane >> 3;
                int nrow = nbase + (np * 2 + (mtx >> 1)) * 8 + (lane & 7);
                int kcol = kt + (mtx & 1) * 8;
                uint32_t bh[4], bl[4];
                ldm_x4(bh, &Bh[nrow][kcol]);
                ldm_x4(bl, &Bl[nrow][kcol]);
                #pragma unroll
                for (int mi = 0; mi < 2; mi++) {
                    #pragma unroll
                    for (int j = 0; j < 2; j++) {
                        int ni = np * 2 + j;
                        mma_bf16(c[mi][ni], ah[mi], bh[2 * j], bh[2 * j + 1]);
                        mma_bf16(c[mi][ni], ah[mi], bl[2 * j], bl[2 * j + 1]);
                        mma_bf16(c[mi][ni], al[mi], bh[2 * j], bh[2 * j + 1]);
                    }
                }
            }
        }
        __syncthreads();
    }

    const int g = lane >> 2;
    const int t = lane & 3;
    #pragma unroll
    for (int ni = 0; ni < 8; ni++) {
        int col = n0 + nbase + ni * 8 + t * 2;
        float2 bb = *(const float2*)(bias + col);
        #pragma unroll
        for (int mi = 0; mi < 2; mi++) {
            int r0 = m0 + mbase + mi * 16 + g;
            if (r0 < M_TOT) {
                float2 v = make_float2(c[mi][ni][0] + bb.x, c[mi][ni][1] + bb.y);
                *(float2*)(outp + (size_t)r0 * ldo + col) = v;
            }
            int r1 = r0 + 8;
            if (r1 < M_TOT) {
                float2 v = make_float2(c[mi][ni][2] + bb.x, c[mi][ni][3] + bb.y);
                *(float2*)(outp + (size_t)r1 * ldo + col) = v;
            }
        }
    }
}

// ---------------------------------------------------------------------------
// K2: windowed attention, tensor-core version.
// Block = (head, window, batch), 128 threads (4 warps), warp owns 16 rows.
// Bias+mask read directly from global (L2-resident) in the softmax.
// ---------------------------------------------------------------------------
__global__ __launch_bounds__(128)
void win_attn_mma_kernel(const float* __restrict__ mask)
{
    const int h  = blockIdx.x;
    const int w  = blockIdx.y;
    const int b  = blockIdx.z;
    const int hy = w >> 5, wx = w & 31;
    const int tid  = threadIdx.x;
    const int lane = tid & 31;
    const int warp = tid >> 5;

    __shared__ __align__(16) __nv_bfloat16 qh[64][40], ql[64][40];
    __shared__ __align__(16) __nv_bfloat16 kh[64][40], kl[64][40];
    __shared__ __align__(16) __nv_bfloat16 vh[64][40], vl[64][40];

    // ---- load q,k,v (fp32 -> bf16 hi/lo) ----
    #pragma unroll
    for (int it = 0; it < 12; it++) {
        int idx = tid + it * 128;        // 0..1535 float4 slots
        int mtx = idx / 512;             // 0=q 1=k 2=v
        int rem = idx - mtx * 512;
        int tok = rem >> 3;
        int c4  = (rem & 7) * 4;
        int wi = tok >> 3, wj = tok & 7;
        int t = (hy * 8 + wi) * 256 + (wx * 8 + wj);
        size_t base = ((size_t)(b * T_TOT + t)) * 384 + (size_t)mtx * 128 + h * 32;
        float4 v4 = *(const float4*)(g_qkv + base + c4);
        float vv[4] = {v4.x, v4.y, v4.z, v4.w};
        __nv_bfloat16* dh = (mtx == 0) ? &qh[0][0] : (mtx == 1) ? &kh[0][0] : &vh[0][0];
        __nv_bfloat16* dl = (mtx == 0) ? &ql[0][0] : (mtx == 1) ? &kl[0][0] : &vl[0][0];
        #pragma unroll
        for (int j = 0; j < 4; j++) {
            __nv_bfloat16 hi = __float2bfloat16(vv[j]);
            dh[tok * 40 + c4 + j] = hi;
            dl[tok * 40 + c4 + j] = __float2bfloat16(vv[j] - __bfloat162float(hi));
        }
    }
    __syncthreads();

    // ---- S = Q K^T : warp rows [warp*16, warp*16+16), 8 n-tiles ----
    const int mrow = warp * 16;
    float sc[8][4] = {};
    #pragma unroll
    for (int kt = 0; kt < 32; kt += 16) {
        uint32_t ah[4], al[4];
        const int arow = mrow + (lane & 15);
        const int acol = kt + ((lane >> 4) << 3);
        ldm_x4(ah, &qh[arow][acol]);
        ldm_x4(al, &ql[arow][acol]);
        #pragma unroll
        for (int np = 0; np < 4; np++) {
            int mtx  = lane >> 3;
            int nrow = (np * 2 + (mtx >> 1)) * 8 + (lane & 7);
            int kcol = kt + (mtx & 1) * 8;
            uint32_t bh[4], bl[4];
            ldm_x4(bh, &kh[nrow][kcol]);
            ldm_x4(bl, &kl[nrow][kcol]);
            #pragma unroll
            for (int j = 0; j < 2; j++) {
                int ni = np * 2 + j;
                mma_bf16(sc[ni], ah, bh[2 * j], bh[2 * j + 1]);
                mma_bf16(sc[ni], ah, bl[2 * j], bl[2 * j + 1]);
                mma_bf16(sc[ni], al, bh[2 * j], bh[2 * j + 1]);
            }
        }
    }

    // ---- softmax in accumulator layout (bias+mask direct from global) ----
    const int g = lane >> 2;      // row within 8-group
    const int t = lane & 3;       // col pair
    const int r0 = mrow + g;      // rows r0 (c0,c1) and r0+8 (c2,c3)
    const float* gbr0 = g_bias + h * (L_WIN * L_WIN) + r0 * 64;
    const float* mkr0 = mask + (size_t)w * (L_WIN * L_WIN) + r0 * 64;
    float mx0 = -1e30f, mx1 = -1e30f;
    #pragma unroll
    for (int j = 0; j < 8; j++) {
        int cbase = j * 8 + t * 2;
        float2 b0 = *(const float2*)(gbr0 + cbase);
        float2 m0 = *(const float2*)(mkr0 + cbase);
        float2 b1 = *(const float2*)(gbr0 + 8 * 64 + cbase);
        float2 m1 = *(const float2*)(mkr0 + 8 * 64 + cbase);
        sc[j][0] = sc[j][0] * SCALE_ + b0.x + m0.x;
        sc[j][1] = sc[j][1] * SCALE_ + b0.y + m0.y;
        sc[j][2] = sc[j][2] * SCALE_ + b1.x + m1.x;
        sc[j][3] = sc[j][3] * SCALE_ + b1.y + m1.y;
        mx0 = fmaxf(mx0, fmaxf(sc[j][0], sc[j][1]));
        mx1 = fmaxf(mx1, fmaxf(sc[j][2], sc[j][3]));
    }
    mx0 = fmaxf(mx0, __shfl_xor_sync(0xffffffffu, mx0, 1));
    mx0 = fmaxf(mx0, __shfl_xor_sync(0xffffffffu, mx0, 2));
    mx1 = fmaxf(mx1, __shfl_xor_sync(0xffffffffu, mx1, 1));
    mx1 = fmaxf(mx1, __shfl_xor_sync(0xffffffffu, mx1, 2));
    float sum0 = 0.f, sum1 = 0.f;
    #pragma unroll
    for (int j = 0; j < 8; j++) {
        sc[j][0] = __expf(sc[j][0] - mx0); sum0 += sc[j][0];
        sc[j][1] = __expf(sc[j][1] - mx0); sum0 += sc[j][1];
        sc[j][2] = __expf(sc[j][2] - mx1); sum1 += sc[j][2];
        sc[j][3] = __expf(sc[j][3] - mx1); sum1 += sc[j][3];
    }
    sum0 += __shfl_xor_sync(0xffffffffu, sum0, 1);
    sum0 += __shfl_xor_sync(0xffffffffu, sum0, 2);
    sum1 += __shfl_xor_sync(0xffffffffu, sum1, 1);
    sum1 += __shfl_xor_sync(0xffffffffu, sum1, 2);
    const float inv0 = 1.0f / sum0, inv1 = 1.0f / sum1;
    #pragma unroll
    for (int j = 0; j < 8; j++) {
        sc[j][0] *= inv0; sc[j][1] *= inv0;
        sc[j][2] *= inv1; sc[j][3] *= inv1;
    }

    // ---- repack P (C-fragments) -> A-fragments, hi/lo split ----
    uint32_t pah[4][4], pal[4][4];
    #pragma unroll
    for (int kt2 = 0; kt2 < 4; kt2++) {
        #pragma unroll
        for (int half = 0; half < 2; half++) {
            const float* cc = sc[2 * kt2 + half];
            float h0 = __bfloat162float(__float2bfloat16(cc[0]));
            float h1 = __bfloat162float(__float2bfloat16(cc[1]));
            float h2 = __bfloat162float(__float2bfloat16(cc[2]));
            float h3 = __bfloat162float(__float2bfloat16(cc[3]));
            pah[kt2][half * 2 + 0] = pack_bf16x2(h0, h1);
            pah[kt2][half * 2 + 1] = pack_bf16x2(h2, h3);
            pal[kt2][half * 2 + 0] = pack_bf16x2(cc[0] - h0, cc[1] - h1);
            pal[kt2][half * 2 + 1] = pack_bf16x2(cc[2] - h2, cc[3] - h3);
        }
    }

    // ---- O = P V : 4 k-tiles (tokens), 4 n-tiles (dims) ----
    float oc[4][4] = {};
    #pragma unroll
    for (int kt2 = 0; kt2 < 4; kt2++) {
        #pragma unroll
        for (int half = 0; half < 2; half++) {
            int mtx = lane >> 3;
            int vrow = kt2 * 16 + (mtx & 1) * 8 + (lane & 7);
            int vcol = half * 16 + (mtx >> 1) * 8;
            uint32_t bh[4], bl[4];
            ldm_x4_t(bh, &vh[vrow][vcol]);
            ldm_x4_t(bl, &vl[vrow][vcol]);
            #pragma unroll
            for (int j = 0; j < 2; j++) {
                int ni = half * 2 + j;
                mma_bf16(oc[ni], pah[kt2], bh[2 * j], bh[2 * j + 1]);
                mma_bf16(oc[ni], pah[kt2], bl[2 * j], bl[2 * j + 1]);
                mma_bf16(oc[ni], pal[kt2], bh[2 * j], bh[2 * j + 1]);
            }
        }
    }

    // ---- store O ----
    #pragma unroll
    for (int rr = 0; rr < 2; rr++) {
        int l = r0 + rr * 8;
        int wi = l >> 3, wj = l & 7;
        int tk = (hy * 8 + wi) * 256 + (wx * 8 + wj);
        float* op = g_ctx + ((size_t)(b * T_TOT + tk)) * 128 + h * 32;
        #pragma unroll
        for (int ni = 0; ni < 4; ni++) {
            float2 v = rr ? make_float2(oc[ni][2], oc[ni][3])
                          : make_float2(oc[ni][0], oc[ni][1]);
            *(float2*)(op + ni * 8 + t * 2) = v;
        }
    }
}

// ---------------------------------------------------------------------------
// K3: det/inter token MHA. Warp-per-query: grid (NH_, B_SZ*2, 25), 4 warps.
// K stored transposed (kt[d][j]), V row-major; softmax across the warp.
// ---------------------------------------------------------------------------
__global__ __launch_bounds__(128)
void tok_attn_kernel()
{
    const int h  = blockIdx.x;
    const int bt = blockIdx.y;           // b*2 + type
    const int qc = blockIdx.z;           // query chunk of 4
    const int b  = bt >> 1, ty = bt & 1;
    const int tbase = N_IMG + ty * TD_;
    const int tid = threadIdx.x, lane = tid & 31, warp = tid >> 5;

    __shared__ __align__(16) float kt[32][104];   // transposed K
    __shared__ __align__(16) float vs[100][32];
    __shared__ float ps[4][104];

    for (int idx = tid; idx < 100 * 8; idx += 128) {
        int tok = idx >> 3;
        int c4  = (idx & 7) * 4;
        size_t base = ((size_t)(b * T_TOT + tbase + tok)) * 384 + h * 32;
        float4 kv = *(const float4*)(g_qkv + base + 128 + c4);
        kt[c4 + 0][tok] = kv.x; kt[c4 + 1][tok] = kv.y;
        kt[c4 + 2][tok] = kv.z; kt[c4 + 3][tok] = kv.w;
        *(float4*)&vs[tok][c4] = *(const float4*)(g_qkv + base + 256 + c4);
    }
    __syncthreads();

    const int q = qc * 4 + warp;         // 0..99 exactly
    // load q row (all lanes hold full vector; 128B redundant, trivial)
    float qv[32];
    {
        const float* qp = g_qkv + ((size_t)(b * T_TOT + tbase + q)) * 384 + h * 32;
        #pragma unroll
        for (int d4 = 0; d4 < 8; d4++) {
            float4 v = *(const float4*)(qp + d4 * 4);
            qv[d4*4+0] = v.x * SCALE_; qv[d4*4+1] = v.y * SCALE_;
            qv[d4*4+2] = v.z * SCALE_; qv[d4*4+3] = v.w * SCALE_;
        }
    }
    // scores: lane handles j = lane, lane+32, lane+64, lane+96 (j<100)
    float s[4];
    float mx = -1e30f;
    #pragma unroll
    for (int m = 0; m < 4; m++) {
        int j = lane + m * 32;
        float acc = -1e30f;
        if (j < 100) {
            acc = 0.f;
            #pragma unroll
            for (int d = 0; d < 32; d++) acc += qv[d] * kt[d][j];
        }
        s[m] = acc;
        mx = fmaxf(mx, acc);
    }
    #pragma unroll
    for (int o = 16; o > 0; o >>= 1)
        mx = fmaxf(mx, __shfl_xor_sync(0xffffffffu, mx, o));
    float sum = 0.f;
    #pragma unroll
    for (int m = 0; m < 4; m++) {
        int j = lane + m * 32;
        if (j < 100) { s[m] = __expf(s[m] - mx); sum += s[m]; }
        else s[m] = 0.f;
    }
    #pragma unroll
    for (int o = 16; o > 0; o >>= 1)
        sum += __shfl_xor_sync(0xffffffffu, sum, o);
    float inv = 1.0f / sum;
    #pragma unroll
    for (int m = 0; m < 4; m++) {
        int j = lane + m * 32;
        if (j < 100) ps[warp][j] = s[m] * inv;
    }
    __syncwarp();

    // O: lane owns dim d = lane
    float o = 0.f;
    #pragma unroll 10
    for (int j = 0; j < 100; j++)
        o += ps[warp][j] * vs[j][lane];
    g_ctx[((size_t)(b * T_TOT + tbase + q)) * 128 + h * 32 + lane] = o;
}

// ---------------------------------------------------------------------------
// kernel_launch
// ---------------------------------------------------------------------------
extern "C" void kernel_launch(void* const* d_in, const int* in_sizes, int n_in,
                              void* d_out, int out_size)
{
    (void)in_sizes; (void)n_in; (void)out_size;
    const float* x        = (const float*)d_in[0];
    const float* det      = (const float*)d_in[1];
    const float* inter    = (const float*)d_in[2];
    const float* mask     = (const float*)d_in[3];
    const float* W_qkv    = (const float*)d_in[4];
    const float* b_qkv    = (const float*)d_in[5];
    const float* W_proj   = (const float*)d_in[6];
    const float* b_proj   = (const float*)d_in[7];
    const float* rel_tab  = (const float*)d_in[8];
    const int*   rel_idx  = (const int*)d_in[9];
    float* out = (float*)d_out;

    const int m_tiles = (M_TOT + 127) / 128;   // 2055

    bias_gather_kernel<<<16, 256>>>(rel_tab, rel_idx);
    mma_gemm_kernel<true><<<dim3(3, m_tiles), 256>>>(x, det, inter,
                                                     W_qkv, b_qkv, nullptr);
    win_attn_mma_kernel<<<dim3(NH_, NWIN, B_SZ), 128>>>(mask);
    tok_attn_kernel<<<dim3(NH_, B_SZ * 2, 25), 128>>>();
    mma_gemm_kernel<false><<<dim3(1, m_tiles), 256>>>(nullptr, nullptr, nullptr,
                                                      W_proj, b_proj, out);
}

// round 8
// speedup vs baseline: 2.4799x; 1.0021x over previous
#include <cuda_runtime.h>
#include <cuda_bf16.h>
#include <cstdint>
#include <cstddef>

// ---------------------------------------------------------------------------
// Problem constants
// ---------------------------------------------------------------------------
#define B_SZ   4
#define NH_    4
#define HD_    32
#define C_DIM  128
#define WS_    8
#define L_WIN  64
#define NWIN   1024        // windows per batch image (32 x 32)
#define N_IMG  65536       // 256*256
#define TD_    100
#define T_TOT  65736       // 65536 + 100 + 100
#define M_TOT  (B_SZ * T_TOT)   // 262944 rows total
#define SCALE_ 0.17677669529663687f   // 32^-0.5

// Scratch (device globals -- no allocation allowed in kernel_launch)
__device__ float g_qkv[(size_t)M_TOT * 384];   // [row][3*C]
__device__ float g_ctx[(size_t)M_TOT * 128];   // attention outputs, proj input
__device__ float g_bias[NH_ * L_WIN * L_WIN];  // pregathered rel-pos bias per head

// ---------------------------------------------------------------------------
// Row pointer for the concatenated token matrix [x | det | inter] per batch
// ---------------------------------------------------------------------------
__device__ __forceinline__ const float* token_row(int r,
                                                  const float* __restrict__ x,
                                                  const float* __restrict__ det,
                                                  const float* __restrict__ inter)
{
    int b = r / T_TOT;
    int t = r - b * T_TOT;
    if (t < N_IMG)  return x     + ((size_t)b * N_IMG + t) * C_DIM;
    t -= N_IMG;
    if (t < TD_)    return det   + ((size_t)b * TD_   + t) * C_DIM;
    return inter + ((size_t)b * TD_ + (t - TD_)) * C_DIM;
}

// ---------------------------------------------------------------------------
// MMA helpers (bf16 m16n8k16, fp32 accumulate)
// ---------------------------------------------------------------------------
__device__ __forceinline__ void mma_bf16(float c[4], const uint32_t a[4],
                                         uint32_t b0, uint32_t b1)
{
    asm volatile(
        "mma.sync.aligned.m16n8k16.row.col.f32.bf16.bf16.f32 "
        "{%0,%1,%2,%3}, {%4,%5,%6,%7}, {%8,%9}, {%0,%1,%2,%3};\n"
        : "+f"(c[0]), "+f"(c[1]), "+f"(c[2]), "+f"(c[3])
        : "r"(a[0]), "r"(a[1]), "r"(a[2]), "r"(a[3]), "r"(b0), "r"(b1));
}

__device__ __forceinline__ void ldm_x4(uint32_t r[4], const void* p)
{
    uint32_t sa = (uint32_t)__cvta_generic_to_shared(p);
    asm volatile("ldmatrix.sync.aligned.m8n8.x4.shared.b16 {%0,%1,%2,%3}, [%4];"
                 : "=r"(r[0]), "=r"(r[1]), "=r"(r[2]), "=r"(r[3]) : "r"(sa));
}

__device__ __forceinline__ void ldm_x4_t(uint32_t r[4], const void* p)
{
    uint32_t sa = (uint32_t)__cvta_generic_to_shared(p);
    asm volatile("ldmatrix.sync.aligned.m8n8.x4.trans.shared.b16 {%0,%1,%2,%3}, [%4];"
                 : "=r"(r[0]), "=r"(r[1]), "=r"(r[2]), "=r"(r[3]) : "r"(sa));
}

// pack two fp32 into bf16x2: low half = e0, high half = e1
__device__ __forceinline__ uint32_t pack_bf16x2(float e0, float e1)
{
    uint32_t r;
    asm("cvt.rn.bf16x2.f32 %0, %1, %2;" : "=r"(r) : "f"(e1), "f"(e0));
    return r;
}

// ---------------------------------------------------------------------------
// K0: pregather the relative-position bias per head: g_bias[h][r*64+c]
// ---------------------------------------------------------------------------
__global__ void bias_gather_kernel(const float* __restrict__ rel_table,
                                   const int*   __restrict__ rel_index)
{
    int idx = blockIdx.x * 256 + threadIdx.x;   // 0..4095
    if (idx < L_WIN * L_WIN) {
        int ri = rel_index[idx];
        #pragma unroll
        for (int h = 0; h < NH_; h++)
            g_bias[h * (L_WIN * L_WIN) + idx] = rel_table[ri * NH_ + h];
    }
}

// ---------------------------------------------------------------------------
// Tensor-core GEMM with bf16 hi/lo split (3 products -> ~fp32-grade accuracy).
// Register-prefetch pipeline + product-major mma order (dependency distance 4).
// ---------------------------------------------------------------------------
template<bool IS_QKV>
__global__ __launch_bounds__(256, 2)
void mma_gemm_kernel(const float* __restrict__ x, const float* __restrict__ det,
                     const float* __restrict__ inter,
                     const float* __restrict__ W, const float* __restrict__ bias,
                     float* __restrict__ out_param)
{
    __shared__ __align__(16) __nv_bfloat16 Ah[128][40];
    __shared__ __align__(16) __nv_bfloat16 Al[128][40];
    __shared__ __align__(16) __nv_bfloat16 Bh[128][40];
    __shared__ __align__(16) __nv_bfloat16 Bl[128][40];

    float* outp = IS_QKV ? g_qkv : out_param;
    const int ldo = IS_QKV ? 384 : 128;

    const int m0   = blockIdx.y * 128;
    const int n0   = blockIdx.x * 128;
    const int tid  = threadIdx.x;
    const int lane = tid & 31;
    const int warp = tid >> 5;
    const int mbase = (warp >> 1) * 32;
    const int nbase = (warp & 1) * 64;

    float c[2][8][4] = {};
    float4 pa[4], pb[4];

    // prologue: load chunk 0
    #pragma unroll
    for (int it = 0; it < 4; it++) {
        int idx = tid + it * 256;
        int row = idx >> 3;
        int c4  = (idx & 7) * 4;
        int r = m0 + row;
        pa[it] = make_float4(0.f, 0.f, 0.f, 0.f);
        if (r < M_TOT) {
            if (IS_QKV) pa[it] = *(const float4*)(token_row(r, x, det, inter) + c4);
            else        pa[it] = *(const float4*)(g_ctx + (size_t)r * 128 + c4);
        }
        pb[it] = *(const float4*)(W + (size_t)(n0 + row) * 128 + c4);
    }

    #pragma unroll
    for (int kc = 0; kc < 4; kc++) {
        // ---- store staged regs -> smem (convert fp32 -> bf16 hi + lo) ----
        #pragma unroll
        for (int it = 0; it < 4; it++) {
            int idx = tid + it * 256;
            int row = idx >> 3;
            int c4  = (idx & 7) * 4;
            float va[4] = {pa[it].x, pa[it].y, pa[it].z, pa[it].w};
            #pragma unroll
            for (int j = 0; j < 4; j++) {
                __nv_bfloat16 h = __float2bfloat16(va[j]);
                Ah[row][c4 + j] = h;
                Al[row][c4 + j] = __float2bfloat16(va[j] - __bfloat162float(h));
            }
            float vb[4] = {pb[it].x, pb[it].y, pb[it].z, pb[it].w};
            #pragma unroll
            for (int j = 0; j < 4; j++) {
                __nv_bfloat16 h = __float2bfloat16(vb[j]);
                Bh[row][c4 + j] = h;
                Bl[row][c4 + j] = __float2bfloat16(vb[j] - __bfloat162float(h));
            }
        }
        __syncthreads();

        // ---- prefetch next chunk (retires under the mma block below) ----
        if (kc < 3) {
            int kk = (kc + 1) * 32;
            #pragma unroll
            for (int it = 0; it < 4; it++) {
                int idx = tid + it * 256;
                int row = idx >> 3;
                int c4  = (idx & 7) * 4;
                int r = m0 + row;
                pa[it] = make_float4(0.f, 0.f, 0.f, 0.f);
                if (r < M_TOT) {
                    if (IS_QKV) pa[it] = *(const float4*)(token_row(r, x, det, inter) + kk + c4);
                    else        pa[it] = *(const float4*)(g_ctx + (size_t)r * 128 + kk + c4);
                }
                pb[it] = *(const float4*)(W + (size_t)(n0 + row) * 128 + kk + c4);
            }
        }

        // ---- compute on current smem chunk ----
        #pragma unroll
        for (int kt = 0; kt < 32; kt += 16) {
            uint32_t ah[2][4], al[2][4];
            const int arow_in = lane & 15;
            const int acol = kt + ((lane >> 4) << 3);
            #pragma unroll
            for (int mi = 0; mi < 2; mi++) {
                ldm_x4(ah[mi], &Ah[mbase + mi * 16 + arow_in][acol]);
                ldm_x4(al[mi], &Al[mbase + mi * 16 + arow_in][acol]);
            }
            #pragma unroll
            for (int np = 0; np < 4; np++) {
                int mtx  = lane >> 3;
                int nrow = nbase + (np * 2 + (mtx >> 1)) * 8 + (lane & 7);
                int kcol = kt + (mtx & 1) * 8;
                uint32_t bh[4], bl[4];
                ldm_x4(bh, &Bh[nrow][kcol]);
                ldm_x4(bl, &Bl[nrow][kcol]);
                // product-major: 4 independent mma between same-acc reuses
                #pragma unroll
                for (int mi = 0; mi < 2; mi++)
                    #pragma unroll
                    for (int j = 0; j < 2; j++)
                        mma_bf16(c[mi][np * 2 + j], ah[mi], bh[2 * j], bh[2 * j + 1]);
                #pragma unroll
                for (int mi = 0; mi < 2; mi++)
                    #pragma unroll
                    for (int j = 0; j < 2; j++)
                        mma_bf16(c[mi][np * 2 + j], ah[mi], bl[2 * j], bl[2 * j + 1]);
                #pragma unroll
                for (int mi = 0; mi < 2; mi++)
                    #pragma unroll
                    for (int j = 0; j < 2; j++)
                        mma_bf16(c[mi][np * 2 + j], al[mi], bh[2 * j], bh[2 * j + 1]);
            }
        }
        __syncthreads();
    }

    const int g = lane >> 2;
    const int t = lane & 3;
    #pragma unroll
    for (int ni = 0; ni < 8; ni++) {
        int col = n0 + nbase + ni * 8 + t * 2;
        float2 bb = *(const float2*)(bias + col);
        #pragma unroll
        for (int mi = 0; mi < 2; mi++) {
            int r0 = m0 + mbase + mi * 16 + g;
            if (r0 < M_TOT) {
                float2 v = make_float2(c[mi][ni][0] + bb.x, c[mi][ni][1] + bb.y);
                *(float2*)(outp + (size_t)r0 * ldo + col) = v;
            }
            int r1 = r0 + 8;
            if (r1 < M_TOT) {
                float2 v = make_float2(c[mi][ni][2] + bb.x, c[mi][ni][3] + bb.y);
                *(float2*)(outp + (size_t)r1 * ldo + col) = v;
            }
        }
    }
}

// ---------------------------------------------------------------------------
// K2: windowed attention, tensor-core version.
// Block = (head, window, batch), 128 threads (4 warps), warp owns 16 rows.
// B fragments hoisted; product-major mma order (dependency distance 8 / 4).
// ---------------------------------------------------------------------------
__global__ __launch_bounds__(128)
void win_attn_mma_kernel(const float* __restrict__ mask)
{
    const int h  = blockIdx.x;
    const int w  = blockIdx.y;
    const int b  = blockIdx.z;
    const int hy = w >> 5, wx = w & 31;
    const int tid  = threadIdx.x;
    const int lane = tid & 31;
    const int warp = tid >> 5;

    __shared__ __align__(16) __nv_bfloat16 qh[64][40], ql[64][40];
    __shared__ __align__(16) __nv_bfloat16 kh[64][40], kl[64][40];
    __shared__ __align__(16) __nv_bfloat16 vh[64][40], vl[64][40];

    // ---- load q,k,v (fp32 -> bf16 hi/lo) ----
    #pragma unroll
    for (int it = 0; it < 12; it++) {
        int idx = tid + it * 128;        // 0..1535 float4 slots
        int mtx = idx / 512;             // 0=q 1=k 2=v
        int rem = idx - mtx * 512;
        int tok = rem >> 3;
        int c4  = (rem & 7) * 4;
        int wi = tok >> 3, wj = tok & 7;
        int t = (hy * 8 + wi) * 256 + (wx * 8 + wj);
        size_t base = ((size_t)(b * T_TOT + t)) * 384 + (size_t)mtx * 128 + h * 32;
        float4 v4 = *(const float4*)(g_qkv + base + c4);
        float vv[4] = {v4.x, v4.y, v4.z, v4.w};
        __nv_bfloat16* dh = (mtx == 0) ? &qh[0][0] : (mtx == 1) ? &kh[0][0] : &vh[0][0];
        __nv_bfloat16* dl = (mtx == 0) ? &ql[0][0] : (mtx == 1) ? &kl[0][0] : &vl[0][0];
        #pragma unroll
        for (int j = 0; j < 4; j++) {
            __nv_bfloat16 hi = __float2bfloat16(vv[j]);
            dh[tok * 40 + c4 + j] = hi;
            dl[tok * 40 + c4 + j] = __float2bfloat16(vv[j] - __bfloat162float(hi));
        }
    }
    __syncthreads();

    // ---- S = Q K^T : warp rows [warp*16, warp*16+16), 8 n-tiles ----
    const int mrow = warp * 16;
    float sc[8][4] = {};
    #pragma unroll
    for (int kt = 0; kt < 32; kt += 16) {
        uint32_t ah[4], al[4];
        const int arow = mrow + (lane & 15);
        const int acol = kt + ((lane >> 4) << 3);
        ldm_x4(ah, &qh[arow][acol]);
        ldm_x4(al, &ql[arow][acol]);
        // hoist all B fragments for this kt
        uint32_t bh[4][4], bl[4][4];
        #pragma unroll
        for (int np = 0; np < 4; np++) {
            int mtx  = lane >> 3;
            int nrow = (np * 2 + (mtx >> 1)) * 8 + (lane & 7);
            int kcol = kt + (mtx & 1) * 8;
            ldm_x4(bh[np], &kh[nrow][kcol]);
            ldm_x4(bl[np], &kl[nrow][kcol]);
        }
        // product-major over all 8 accumulators: distance 8
        #pragma unroll
        for (int np = 0; np < 4; np++)
            #pragma unroll
            for (int j = 0; j < 2; j++)
                mma_bf16(sc[np * 2 + j], ah, bh[np][2 * j], bh[np][2 * j + 1]);
        #pragma unroll
        for (int np = 0; np < 4; np++)
            #pragma unroll
            for (int j = 0; j < 2; j++)
                mma_bf16(sc[np * 2 + j], ah, bl[np][2 * j], bl[np][2 * j + 1]);
        #pragma unroll
        for (int np = 0; np < 4; np++)
            #pragma unroll
            for (int j = 0; j < 2; j++)
                mma_bf16(sc[np * 2 + j], al, bh[np][2 * j], bh[np][2 * j + 1]);
    }

    // ---- softmax in accumulator layout (bias+mask direct from global) ----
    const int g = lane >> 2;      // row within 8-group
    const int t = lane & 3;       // col pair
    const int r0 = mrow + g;      // rows r0 (c0,c1) and r0+8 (c2,c3)
    const float* gbr0 = g_bias + h * (L_WIN * L_WIN) + r0 * 64;
    const float* mkr0 = mask + (size_t)w * (L_WIN * L_WIN) + r0 * 64;
    float mx0 = -1e30f, mx1 = -1e30f;
    #pragma unroll
    for (int j = 0; j < 8; j++) {
        int cbase = j * 8 + t * 2;
        float2 b0 = *(const float2*)(gbr0 + cbase);
        float2 m0 = *(const float2*)(mkr0 + cbase);
        float2 b1 = *(const float2*)(gbr0 + 8 * 64 + cbase);
        float2 m1 = *(const float2*)(mkr0 + 8 * 64 + cbase);
        sc[j][0] = sc[j][0] * SCALE_ + b0.x + m0.x;
        sc[j][1] = sc[j][1] * SCALE_ + b0.y + m0.y;
        sc[j][2] = sc[j][2] * SCALE_ + b1.x + m1.x;
        sc[j][3] = sc[j][3] * SCALE_ + b1.y + m1.y;
        mx0 = fmaxf(mx0, fmaxf(sc[j][0], sc[j][1]));
        mx1 = fmaxf(mx1, fmaxf(sc[j][2], sc[j][3]));
    }
    mx0 = fmaxf(mx0, __shfl_xor_sync(0xffffffffu, mx0, 1));
    mx0 = fmaxf(mx0, __shfl_xor_sync(0xffffffffu, mx0, 2));
    mx1 = fmaxf(mx1, __shfl_xor_sync(0xffffffffu, mx1, 1));
    mx1 = fmaxf(mx1, __shfl_xor_sync(0xffffffffu, mx1, 2));
    float sum0 = 0.f, sum1 = 0.f;
    #pragma unroll
    for (int j = 0; j < 8; j++) {
        sc[j][0] = __expf(sc[j][0] - mx0); sum0 += sc[j][0];
        sc[j][1] = __expf(sc[j][1] - mx0); sum0 += sc[j][1];
        sc[j][2] = __expf(sc[j][2] - mx1); sum1 += sc[j][2];
        sc[j][3] = __expf(sc[j][3] - mx1); sum1 += sc[j][3];
    }
    sum0 += __shfl_xor_sync(0xffffffffu, sum0, 1);
    sum0 += __shfl_xor_sync(0xffffffffu, sum0, 2);
    sum1 += __shfl_xor_sync(0xffffffffu, sum1, 1);
    sum1 += __shfl_xor_sync(0xffffffffu, sum1, 2);
    const float inv0 = 1.0f / sum0, inv1 = 1.0f / sum1;
    #pragma unroll
    for (int j = 0; j < 8; j++) {
        sc[j][0] *= inv0; sc[j][1] *= inv0;
        sc[j][2] *= inv1; sc[j][3] *= inv1;
    }

    // ---- repack P (C-fragments) -> A-fragments, hi/lo split ----
    uint32_t pah[4][4], pal[4][4];
    #pragma unroll
    for (int kt2 = 0; kt2 < 4; kt2++) {
        #pragma unroll
        for (int half = 0; half < 2; half++) {
            const float* cc = sc[2 * kt2 + half];
            float h0 = __bfloat162float(__float2bfloat16(cc[0]));
            float h1 = __bfloat162float(__float2bfloat16(cc[1]));
            float h2 = __bfloat162float(__float2bfloat16(cc[2]));
            float h3 = __bfloat162float(__float2bfloat16(cc[3]));
            pah[kt2][half * 2 + 0] = pack_bf16x2(h0, h1);
            pah[kt2][half * 2 + 1] = pack_bf16x2(h2, h3);
            pal[kt2][half * 2 + 0] = pack_bf16x2(cc[0] - h0, cc[1] - h1);
            pal[kt2][half * 2 + 1] = pack_bf16x2(cc[2] - h2, cc[3] - h3);
        }
    }

    // ---- O = P V : 4 k-tiles (tokens), 4 n-tiles (dims) ----
    float oc[4][4] = {};
    #pragma unroll
    for (int kt2 = 0; kt2 < 4; kt2++) {
        int mtx = lane >> 3;
        int vrow = kt2 * 16 + (mtx & 1) * 8 + (lane & 7);
        uint32_t bh[2][4], bl[2][4];
        #pragma unroll
        for (int half = 0; half < 2; half++) {
            int vcol = half * 16 + (mtx >> 1) * 8;
            ldm_x4_t(bh[half], &vh[vrow][vcol]);
            ldm_x4_t(bl[half], &vl[vrow][vcol]);
        }
        // product-major over 4 accumulators: distance 4
        #pragma unroll
        for (int half = 0; half < 2; half++)
            #pragma unroll
            for (int j = 0; j < 2; j++)
                mma_bf16(oc[half * 2 + j], pah[kt2], bh[half][2 * j], bh[half][2 * j + 1]);
        #pragma unroll
        for (int half = 0; half < 2; half++)
            #pragma unroll
            for (int j = 0; j < 2; j++)
                mma_bf16(oc[half * 2 + j], pah[kt2], bl[half][2 * j], bl[half][2 * j + 1]);
        #pragma unroll
        for (int half = 0; half < 2; half++)
            #pragma unroll
            for (int j = 0; j < 2; j++)
                mma_bf16(oc[half * 2 + j], pal[kt2], bh[half][2 * j], bh[half][2 * j + 1]);
    }

    // ---- store O ----
    #pragma unroll
    for (int rr = 0; rr < 2; rr++) {
        int l = r0 + rr * 8;
        int wi = l >> 3, wj = l & 7;
        int tk = (hy * 8 + wi) * 256 + (wx * 8 + wj);
        float* op = g_ctx + ((size_t)(b * T_TOT + tk)) * 128 + h * 32;
        #pragma unroll
        for (int ni = 0; ni < 4; ni++) {
            float2 v = rr ? make_float2(oc[ni][2], oc[ni][3])
                          : make_float2(oc[ni][0], oc[ni][1]);
            *(float2*)(op + ni * 8 + t * 2) = v;
        }
    }
}

// ---------------------------------------------------------------------------
// K3: det/inter token MHA. Warp-per-query: grid (NH_, B_SZ*2, 25), 4 warps.
// ---------------------------------------------------------------------------
__global__ __launch_bounds__(128)
void tok_attn_kernel()
{
    const int h  = blockIdx.x;
    const int bt = blockIdx.y;           // b*2 + type
    const int qc = blockIdx.z;           // query chunk of 4
    const int b  = bt >> 1, ty = bt & 1;
    const int tbase = N_IMG + ty * TD_;
    const int tid = threadIdx.x, lane = tid & 31, warp = tid >> 5;

    __shared__ __align__(16) float kt[32][104];   // transposed K
    __shared__ __align__(16) float vs[100][32];
    __shared__ float ps[4][104];

    for (int idx = tid; idx < 100 * 8; idx += 128) {
        int tok = idx >> 3;
        int c4  = (idx & 7) * 4;
        size_t base = ((size_t)(b * T_TOT + tbase + tok)) * 384 + h * 32;
        float4 kv = *(const float4*)(g_qkv + base + 128 + c4);
        kt[c4 + 0][tok] = kv.x; kt[c4 + 1][tok] = kv.y;
        kt[c4 + 2][tok] = kv.z; kt[c4 + 3][tok] = kv.w;
        *(float4*)&vs[tok][c4] = *(const float4*)(g_qkv + base + 256 + c4);
    }
    __syncthreads();

    const int q = qc * 4 + warp;         // 0..99 exactly
    float qv[32];
    {
        const float* qp = g_qkv + ((size_t)(b * T_TOT + tbase + q)) * 384 + h * 32;
        #pragma unroll
        for (int d4 = 0; d4 < 8; d4++) {
            float4 v = *(const float4*)(qp + d4 * 4);
            qv[d4*4+0] = v.x * SCALE_; qv[d4*4+1] = v.y * SCALE_;
            qv[d4*4+2] = v.z * SCALE_; qv[d4*4+3] = v.w * SCALE_;
        }
    }
    float s[4];
    float mx = -1e30f;
    #pragma unroll
    for (int m = 0; m < 4; m++) {
        int j = lane + m * 32;
        float acc = -1e30f;
        if (j < 100) {
            acc = 0.f;
            #pragma unroll
            for (int d = 0; d < 32; d++) acc += qv[d] * kt[d][j];
        }
        s[m] = acc;
        mx = fmaxf(mx, acc);
    }
    #pragma unroll
    for (int o = 16; o > 0; o >>= 1)
        mx = fmaxf(mx, __shfl_xor_sync(0xffffffffu, mx, o));
    float sum = 0.f;
    #pragma unroll
    for (int m = 0; m < 4; m++) {
        int j = lane + m * 32;
        if (j < 100) { s[m] = __expf(s[m] - mx); sum += s[m]; }
        else s[m] = 0.f;
    }
    #pragma unroll
    for (int o = 16; o > 0; o >>= 1)
        sum += __shfl_xor_sync(0xffffffffu, sum, o);
    float inv = 1.0f / sum;
    #pragma unroll
    for (int m = 0; m < 4; m++) {
        int j = lane + m * 32;
        if (j < 100) ps[warp][j] = s[m] * inv;
    }
    __syncwarp();

    float o = 0.f;
    #pragma unroll 10
    for (int j = 0; j < 100; j++)
        o += ps[warp][j] * vs[j][lane];
    g_ctx[((size_t)(b * T_TOT + tbase + q)) * 128 + h * 32 + lane] = o;
}

// ---------------------------------------------------------------------------
// kernel_launch
// ---------------------------------------------------------------------------
extern "C" void kernel_launch(void* const* d_in, const int* in_sizes, int n_in,
                              void* d_out, int out_size)
{
    (void)in_sizes; (void)n_in; (void)out_size;
    const float* x        = (const float*)d_in[0];
    const float* det      = (const float*)d_in[1];
    const float* inter    = (const float*)d_in[2];
    const float* mask     = (const float*)d_in[3];
    const float* W_qkv    = (const float*)d_in[4];
    const float* b_qkv    = (const float*)d_in[5];
    const float* W_proj   = (const float*)d_in[6];
    const float* b_proj   = (const float*)d_in[7];
    const float* rel_tab  = (const float*)d_in[8];
    const int*   rel_idx  = (const int*)d_in[9];
    float* out = (float*)d_out;

    const int m_tiles = (M_TOT + 127) / 128;   // 2055

    bias_gather_kernel<<<16, 256>>>(rel_tab, rel_idx);
    mma_gemm_kernel<true><<<dim3(3, m_tiles), 256>>>(x, det, inter,
                                                     W_qkv, b_qkv, nullptr);
    win_attn_mma_kernel<<<dim3(NH_, NWIN, B_SZ), 128>>>(mask);
    tok_attn_kernel<<<dim3(NH_, B_SZ * 2, 25), 128>>>();
    mma_gemm_kernel<false><<<dim3(1, m_tiles), 256>>>(nullptr, nullptr, nullptr,
                                                      W_proj, b_proj, out);
}